// round 11
// baseline (speedup 1.0000x reference)
#include <cuda_runtime.h>
#include <cuda_bf16.h>
#include <cstdint>
#include <math.h>

#define T 2048
#define H 2048
#define QKV_N 3072
#define NH 32
#define NKV 8
#define QM 4
#define HD 64
#define SW 128
#define QT 32
#define MAXK (SW + QT)   // 160 keys max per query tile

// ---- GEMM tiling (mma.sync bf16): CTA 128x128, 8 warps of 64x32 ----
#define BM 128
#define BN 128
#define BK 32
#define RS 80                       // padded smem row stride in bytes
#define STAGE_A (128 * RS)          // 10240 B
#define STAGE (2 * STAGE_A)         // 20480 B
#define NSTAGE 3
#define GEMM_SMEM (NSTAGE * STAGE)  // 61440 B -> 3 CTAs/SM (with 84 regs)

// ---- attention smem (32-bit words): K + V + P only (Q staged thru P) ----
#define KSTR 68
#define VSTR 72
#define PSTR 36
#define ATT_K_W (MAXK * KSTR)             // 10880
#define ATT_V_W (MAXK * VSTR)             // 11520
#define ATT_P_W (4 * 32 * PSTR)           // 4608
#define ATT_SMEM ((ATT_K_W + ATT_V_W + ATT_P_W) * 4)  // 108032 B -> 2 CTAs/SM

// ---------------- scratch (device globals; no allocation allowed) ----------
__device__ __nv_bfloat16 g_act[(size_t)T * H];          // rmsnorm output (bf16)
__device__ float        g_qkv[(size_t)T * QKV_N];       // qkv output (fp32, pre-rope)
__device__ __nv_bfloat16 g_attn[(size_t)T * H];         // attention output (bf16)
__device__ __nv_bfloat16 g_qkvw_t[(size_t)QKV_N * H];   // qkv weight [N,K] bf16
__device__ __nv_bfloat16 g_outw_t[(size_t)H * H];       // out weight [N,K] bf16

// ---------------- helpers ----------------------------------------------
__device__ __forceinline__ uint32_t smem_u32(const void* p) {
    uint32_t a;
    asm("{ .reg .u64 t; cvta.to.shared.u64 t, %1; cvt.u32.u64 %0, t; }" : "=r"(a) : "l"(p));
    return a;
}
__device__ __forceinline__ void cp_async16(uint32_t saddr, const void* gaddr) {
    asm volatile("cp.async.cg.shared.global [%0], [%1], 16;" :: "r"(saddr), "l"(gaddr));
}
__device__ __forceinline__ void ldsm4(uint32_t* r, uint32_t a) {
    asm volatile("ldmatrix.sync.aligned.m8n8.x4.shared.b16 {%0,%1,%2,%3}, [%4];"
        : "=r"(r[0]), "=r"(r[1]), "=r"(r[2]), "=r"(r[3]) : "r"(a));
}
__device__ __forceinline__ void mma16816(float* c, const uint32_t* a, const uint32_t* b) {
    asm volatile("mma.sync.aligned.m16n8k16.row.col.f32.bf16.bf16.f32 "
        "{%0,%1,%2,%3}, {%4,%5,%6,%7}, {%8,%9}, {%0,%1,%2,%3};"
        : "+f"(c[0]), "+f"(c[1]), "+f"(c[2]), "+f"(c[3])
        : "r"(a[0]), "r"(a[1]), "r"(a[2]), "r"(a[3]), "r"(b[0]), "r"(b[1]));
}
__device__ __forceinline__ void mma_tf32(float* c, const uint32_t* a, const uint32_t* b) {
    asm volatile("mma.sync.aligned.m16n8k8.row.col.f32.tf32.tf32.f32 "
        "{%0,%1,%2,%3}, {%4,%5,%6,%7}, {%8,%9}, {%0,%1,%2,%3};"
        : "+f"(c[0]), "+f"(c[1]), "+f"(c[2]), "+f"(c[3])
        : "r"(a[0]), "r"(a[1]), "r"(a[2]), "r"(a[3]), "r"(b[0]), "r"(b[1]));
}
__device__ __forceinline__ uint32_t f2tf32(float f) {
    uint32_t u;
    asm("cvt.rna.tf32.f32 %0, %1;" : "=r"(u) : "f"(f));
    return u;
}
// exp(x) without MUFU: 2^t with t = x*log2(e), |frac| <= 0.5, degree-5 poly.
__device__ __forceinline__ float fast_exp(float x) {
    float t = x * 1.4426950408889634f;
    int i = __float2int_rn(t);
    float f = t - (float)i;
    float p = 1.3333558146e-3f;
    p = fmaf(p, f, 9.6181291076e-3f);
    p = fmaf(p, f, 5.5504108664e-2f);
    p = fmaf(p, f, 2.4022650696e-1f);
    p = fmaf(p, f, 6.9314718056e-1f);
    p = fmaf(p, f, 1.0f);
    float sc = __int_as_float((i + 127) << 23);
    return p * sc;
}

// ---------------- fused prep: rmsnorm + both weight transposes --------------
__device__ __forceinline__ void transpose_body(const float* __restrict__ S,
                                               __nv_bfloat16* __restrict__ D,
                                               int K, int N, int n0, int k0) {
    __shared__ float t[32][33];
    int tx = threadIdx.x & 31, ty = threadIdx.x >> 5;
    #pragma unroll
    for (int i = 0; i < 32; i += 8)
        t[ty + i][tx] = S[(size_t)(k0 + ty + i) * N + n0 + tx];
    __syncthreads();
    #pragma unroll
    for (int i = 0; i < 32; i += 8)
        D[(size_t)(n0 + ty + i) * K + k0 + tx] = __float2bfloat16(t[tx][ty + i]);
}

__global__ __launch_bounds__(256) void prep_kernel(const float* __restrict__ x,
                                                   const float* __restrict__ scale,
                                                   const float* __restrict__ qkvw,
                                                   const float* __restrict__ outw) {
    int b = blockIdx.x;
    if (b < T) {
        int row = b;
        const float4* xr4 = (const float4*)(x + (size_t)row * H);
        int tid = threadIdx.x;
        float4 v0 = xr4[tid], v1 = xr4[tid + 256];
        float ss = v0.x * v0.x + v0.y * v0.y + v0.z * v0.z + v0.w * v0.w
                 + v1.x * v1.x + v1.y * v1.y + v1.z * v1.z + v1.w * v1.w;
        for (int o = 16; o > 0; o >>= 1) ss += __shfl_xor_sync(0xffffffffu, ss, o);
        __shared__ float red[8];
        int wid = tid >> 5, lane = tid & 31;
        if (lane == 0) red[wid] = ss;
        __syncthreads();
        __shared__ float s_inv;
        if (tid == 0) {
            float t = 0.f;
            #pragma unroll
            for (int i = 0; i < 8; i++) t += red[i];
            s_inv = rsqrtf(t * (1.0f / (float)H) + 1e-5f);
        }
        __syncthreads();
        float inv = s_inv;
        const float4* sc4 = (const float4*)scale;
        float4 s0 = sc4[tid], s1 = sc4[tid + 256];
        __nv_bfloat162* o2 = (__nv_bfloat162*)(g_act + (size_t)row * H);
        o2[2 * tid]     = __floats2bfloat162_rn(v0.x * inv * s0.x, v0.y * inv * s0.y);
        o2[2 * tid + 1] = __floats2bfloat162_rn(v0.z * inv * s0.z, v0.w * inv * s0.w);
        o2[2 * (tid + 256)]     = __floats2bfloat162_rn(v1.x * inv * s1.x, v1.y * inv * s1.y);
        o2[2 * (tid + 256) + 1] = __floats2bfloat162_rn(v1.z * inv * s1.z, v1.w * inv * s1.w);
    } else if (b < T + (QKV_N / 32) * (H / 32)) {
        int bx = b - T;
        transpose_body(qkvw, g_qkvw_t, H, QKV_N, (bx % (QKV_N / 32)) * 32, (bx / (QKV_N / 32)) * 32);
    } else {
        int bx = b - T - (QKV_N / 32) * (H / 32);
        transpose_body(outw, g_outw_t, H, H, (bx % (H / 32)) * 32, (bx / (H / 32)) * 32);
    }
}

// ---------------- bf16 mma.sync GEMM: C = A[M,K] @ Bt[N,K]^T + bias (+resid)
// CTA 128x128x32, 8 warps (2x4) of 64x32, 3-stage cp.async, 3 CTAs/SM.
__global__ __launch_bounds__(256, 3) void gemm_tc_kernel(const __nv_bfloat16* __restrict__ A,
                                                         const __nv_bfloat16* __restrict__ Bt,
                                                         const float* __restrict__ bias,
                                                         const float* __restrict__ resid,
                                                         float* __restrict__ C,
                                                         int N, int K) {
    extern __shared__ char smem[];
    uint32_t sbase = smem_u32(smem);

    int tid = threadIdx.x;
    int wid = tid >> 5, lane = tid & 31;
    int wm = wid & 1;
    int wn = wid >> 1;
    int bm = blockIdx.y * BM, bn = blockIdx.x * BN;

    float acc[4][4][4];
    #pragma unroll
    for (int i = 0; i < 4; i++)
        #pragma unroll
        for (int j = 0; j < 4; j++)
            #pragma unroll
            for (int e = 0; e < 4; e++) acc[i][j][e] = 0.f;

    const int nk = K / BK;

    auto load_stage = [&](int it) {
        uint32_t sb = sbase + (it % NSTAGE) * STAGE;
        const __nv_bfloat16* Ag = A + (size_t)bm * K + it * BK;
        const __nv_bfloat16* Bg = Bt + (size_t)bn * K + it * BK;
        #pragma unroll
        for (int i = 0; i < 2; i++) {
            int c = tid + i * 256;
            int row = c >> 2, h = c & 3;
            cp_async16(sb + row * RS + h * 16, Ag + (size_t)row * K + h * 8);
        }
        #pragma unroll
        for (int i = 0; i < 2; i++) {
            int c = tid + i * 256;
            int row = c >> 2, h = c & 3;
            cp_async16(sb + STAGE_A + row * RS + h * 16, Bg + (size_t)row * K + h * 8);
        }
        asm volatile("cp.async.commit_group;" ::: "memory");
    };

    load_stage(0);
    load_stage(1);

    uint32_t aoff = (uint32_t)(lane & 15) * RS + (uint32_t)(lane >> 4) * 16;
    uint32_t boff = (uint32_t)(wn * 32 + ((lane >> 4) << 3) + (lane & 7)) * RS
                  + (uint32_t)((lane >> 3) & 1) * 16;

    auto mma4 = [&](int mi, const uint32_t* a, const uint32_t* b0, const uint32_t* b1) {
        mma16816(acc[mi][0], a, b0);
        mma16816(acc[mi][1], a, b0 + 2);
        mma16816(acc[mi][2], a, b1);
        mma16816(acc[mi][3], a, b1 + 2);
    };

    for (int it = 0; it < nk; it++) {
        asm volatile("cp.async.wait_group 1;" ::: "memory");
        __syncthreads();
        // safe: writes buffer (it-1)%NSTAGE, consumed last iter (all warps past it via the sync)
        if (it + 2 < nk) load_stage(it + 2);
        else asm volatile("cp.async.commit_group;" ::: "memory");

        uint32_t sb = sbase + (it % NSTAGE) * STAGE;
        uint32_t aBase = sb + (uint32_t)(wm * 64) * RS + aoff;
        uint32_t bBase = sb + STAGE_A + boff;

        uint32_t bA0[4], bA1[4], bB0[4], bB1[4], aP[4], aQ[4];
        ldsm4(bA0, bBase);
        ldsm4(bA1, bBase + (uint32_t)(16 * RS));
        ldsm4(aP, aBase);

        ldsm4(aQ, aBase + (uint32_t)(16 * RS));
        mma4(0, aP, bA0, bA1);

        ldsm4(aP, aBase + (uint32_t)(32 * RS));
        mma4(1, aQ, bA0, bA1);

        ldsm4(aQ, aBase + (uint32_t)(48 * RS));
        ldsm4(bB0, bBase + 32);
        mma4(2, aP, bA0, bA1);

        ldsm4(bB1, bBase + (uint32_t)(16 * RS) + 32);
        ldsm4(aP, aBase + 32);
        mma4(3, aQ, bA0, bA1);

        ldsm4(aQ, aBase + (uint32_t)(16 * RS) + 32);
        mma4(0, aP, bB0, bB1);

        ldsm4(aP, aBase + (uint32_t)(32 * RS) + 32);
        mma4(1, aQ, bB0, bB1);

        ldsm4(aQ, aBase + (uint32_t)(48 * RS) + 32);
        mma4(2, aP, bB0, bB1);

        mma4(3, aQ, bB0, bB1);
    }

    int rq = lane >> 2, cq = (lane & 3) * 2;
    #pragma unroll
    for (int mi = 0; mi < 4; mi++) {
        int r0 = bm + wm * 64 + mi * 16 + rq;
        #pragma unroll
        for (int half = 0; half < 2; half++) {
            int r = r0 + half * 8;
            float* crow = C + (size_t)r * N;
            const float* rrow = resid ? resid + (size_t)r * N : (const float*)0;
            #pragma unroll
            for (int nj = 0; nj < 4; nj++) {
                int c = bn + wn * 32 + nj * 8 + cq;
                float2 v;
                v.x = acc[mi][nj][half * 2 + 0] + bias[c];
                v.y = acc[mi][nj][half * 2 + 1] + bias[c + 1];
                if (rrow) { v.x += rrow[c]; v.y += rrow[c + 1]; }
                *(float2*)&crow[c] = v;
            }
        }
    }
}

// ---------------- tensor-core windowed GQA attention (rope fused) -----------
__global__ __launch_bounds__(128, 2) void attn_tc_kernel(const float* __restrict__ sinks,
                                                         const float* __restrict__ cosb,
                                                         const float* __restrict__ sinb) {
    extern __shared__ uint32_t shu[];
    uint32_t* Ku = shu;                       // [160][KSTR]
    uint32_t* Vu = Ku + ATT_K_W;              // [160][VSTR]
    uint32_t* Pu = Vu + ATT_V_W;              // [4][32][PSTR]

    int nkv = blockIdx.y;
    int q0 = blockIdx.x * QT;
    int ks = q0 - SW; if (ks < 0) ks = 0;
    int nk = q0 + QT - ks;                    // multiple of 32
    int nchunk = nk >> 5;

    int tid = threadIdx.x, w = tid >> 5, lane = tid & 31;

    const float* kbase = g_qkv + H + nkv * HD;
    for (int idx = tid; idx < nk * 8; idx += 128) {
        int c = idx & 7;
        int row = idx >> 3;
        int t = ks + row;
        const float* base = kbase + (size_t)t * QKV_N;
        float4 lo = *(const float4*)(base + c * 4);
        float4 hi = *(const float4*)(base + 32 + c * 4);
        float4 cs = *(const float4*)(cosb + t * 32 + c * 4);
        float4 sn = *(const float4*)(sinb + t * 32 + c * 4);
        uint32_t* dst = Ku + row * KSTR + c * 4;
        dst[0] = f2tf32(lo.x * cs.x - hi.x * sn.x);
        dst[1] = f2tf32(lo.y * cs.y - hi.y * sn.y);
        dst[2] = f2tf32(lo.z * cs.z - hi.z * sn.z);
        dst[3] = f2tf32(lo.w * cs.w - hi.w * sn.w);
        dst[32] = f2tf32(hi.x * cs.x + lo.x * sn.x);
        dst[33] = f2tf32(hi.y * cs.y + lo.y * sn.y);
        dst[34] = f2tf32(hi.z * cs.z + lo.z * sn.z);
        dst[35] = f2tf32(hi.w * cs.w + lo.w * sn.w);
    }
    const float* vbase = g_qkv + H + NKV * HD + nkv * HD;
    for (int idx = tid; idx < nk * 16; idx += 128) {
        int r0 = idx >> 4, c4 = (idx & 15) << 2;
        float4 v = *(const float4*)(vbase + (size_t)(ks + r0) * QKV_N + c4);
        uint32_t* dst = Vu + r0 * VSTR + c4;
        dst[0] = f2tf32(v.x); dst[1] = f2tf32(v.y);
        dst[2] = f2tf32(v.z); dst[3] = f2tf32(v.w);
    }
    __syncthreads();

    int r = lane >> 2, kq = lane & 3;
    uint32_t* Pw = Pu + w * 32 * PSTR;

    // per-warp Q staging through own P slab: rope + scale + tf32, two halves
    uint32_t af[2][8][4];
    {
        int row = lane;
        int tq = q0 + row;
        const float* qbase = g_qkv + (size_t)tq * QKV_N + (nkv * QM + w) * HD;
        #pragma unroll
        for (int h = 0; h < 2; h++) {
            #pragma unroll
            for (int c4 = 0; c4 < 8; c4++) {
                float4 lo = *(const float4*)(qbase + c4 * 4);
                float4 hi = *(const float4*)(qbase + 32 + c4 * 4);
                float4 cs = *(const float4*)(cosb + tq * 32 + c4 * 4);
                float4 sn = *(const float4*)(sinb + tq * 32 + c4 * 4);
                uint4 o;
                if (h == 0) {
                    o.x = f2tf32((lo.x * cs.x - hi.x * sn.x) * 0.125f);
                    o.y = f2tf32((lo.y * cs.y - hi.y * sn.y) * 0.125f);
                    o.z = f2tf32((lo.z * cs.z - hi.z * sn.z) * 0.125f);
                    o.w = f2tf32((lo.w * cs.w - hi.w * sn.w) * 0.125f);
                } else {
                    o.x = f2tf32((hi.x * cs.x + lo.x * sn.x) * 0.125f);
                    o.y = f2tf32((hi.y * cs.y + lo.y * sn.y) * 0.125f);
                    o.z = f2tf32((hi.z * cs.z + lo.z * sn.z) * 0.125f);
                    o.w = f2tf32((hi.w * cs.w + lo.w * sn.w) * 0.125f);
                }
                *(uint4*)&Pw[row * PSTR + c4 * 4] = o;
            }
            __syncwarp();
            #pragma unroll
            for (int mt = 0; mt < 2; mt++)
                #pragma unroll
                for (int kt2 = 0; kt2 < 4; kt2++) {
                    int kt = h * 4 + kt2;
                    af[mt][kt][0] = Pw[(mt * 16 + r) * PSTR + kt2 * 8 + kq];
                    af[mt][kt][1] = Pw[(mt * 16 + r + 8) * PSTR + kt2 * 8 + kq];
                    af[mt][kt][2] = Pw[(mt * 16 + r) * PSTR + kt2 * 8 + kq + 4];
                    af[mt][kt][3] = Pw[(mt * 16 + r + 8) * PSTR + kt2 * 8 + kq + 4];
                }
            __syncwarp();
        }
    }

    float accO[2][8][4];
    #pragma unroll
    for (int mt = 0; mt < 2; mt++)
        #pragma unroll
        for (int nt = 0; nt < 8; nt++)
            #pragma unroll
            for (int e = 0; e < 4; e++) accO[mt][nt][e] = 0.f;
    float lsum[2][2] = {{0.f, 0.f}, {0.f, 0.f}};

    for (int c = 0; c < nchunk; c++) {
        float S[2][4][4];
        #pragma unroll
        for (int mt = 0; mt < 2; mt++)
            #pragma unroll
            for (int nt = 0; nt < 4; nt++)
                #pragma unroll
                for (int e = 0; e < 4; e++) S[mt][nt][e] = 0.f;
        #pragma unroll
        for (int nt = 0; nt < 4; nt++) {
            int key = c * 32 + nt * 8 + r;
            #pragma unroll
            for (int kt = 0; kt < 8; kt++) {
                uint32_t b[2];
                b[0] = Ku[key * KSTR + kt * 8 + kq];
                b[1] = Ku[key * KSTR + kt * 8 + kq + 4];
                mma_tf32(S[0][nt], af[0][kt], b);
                mma_tf32(S[1][nt], af[1][kt], b);
            }
        }
        #pragma unroll
        for (int mt = 0; mt < 2; mt++)
            #pragma unroll
            for (int nt = 0; nt < 4; nt++) {
                #pragma unroll
                for (int e = 0; e < 4; e++) {
                    int half = e >> 1;
                    int q = q0 + mt * 16 + r + half * 8;
                    int kp = ks + c * 32 + nt * 8 + 2 * kq + (e & 1);
                    float p = fast_exp(S[mt][nt][e]);
                    p = (kp <= q && q - kp <= SW) ? p : 0.f;
                    lsum[mt][half] += p;
                    S[mt][nt][e] = p;
                }
                *(uint2*)&Pw[(mt * 16 + r) * PSTR + nt * 8 + 2 * kq] =
                    make_uint2(f2tf32(S[mt][nt][0]), f2tf32(S[mt][nt][1]));
                *(uint2*)&Pw[(mt * 16 + r + 8) * PSTR + nt * 8 + 2 * kq] =
                    make_uint2(f2tf32(S[mt][nt][2]), f2tf32(S[mt][nt][3]));
            }
        __syncwarp();
        #pragma unroll
        for (int kt = 0; kt < 4; kt++) {
            uint32_t pa[2][4];
            #pragma unroll
            for (int mt = 0; mt < 2; mt++) {
                pa[mt][0] = Pw[(mt * 16 + r) * PSTR + kt * 8 + kq];
                pa[mt][1] = Pw[(mt * 16 + r + 8) * PSTR + kt * 8 + kq];
                pa[mt][2] = Pw[(mt * 16 + r) * PSTR + kt * 8 + kq + 4];
                pa[mt][3] = Pw[(mt * 16 + r + 8) * PSTR + kt * 8 + kq + 4];
            }
            int key = c * 32 + kt * 8;
            #pragma unroll
            for (int nt = 0; nt < 8; nt++) {
                uint32_t b[2];
                b[0] = Vu[(key + kq) * VSTR + nt * 8 + r];
                b[1] = Vu[(key + kq + 4) * VSTR + nt * 8 + r];
                mma_tf32(accO[0][nt], pa[0], b);
                mma_tf32(accO[1][nt], pa[1], b);
            }
        }
        __syncwarp();
    }

    float sk = fast_exp(sinks[nkv * QM + w]);
    float inv[2][2];
    #pragma unroll
    for (int mt = 0; mt < 2; mt++)
        #pragma unroll
        for (int half = 0; half < 2; half++) {
            float l = lsum[mt][half];
            l += __shfl_xor_sync(0xffffffffu, l, 1);
            l += __shfl_xor_sync(0xffffffffu, l, 2);
            inv[mt][half] = 1.f / (l + sk);
        }

    int headcol = (nkv * QM + w) * HD;
    #pragma unroll
    for (int mt = 0; mt < 2; mt++)
        #pragma unroll
        for (int nt = 0; nt < 8; nt++) {
            int col = headcol + nt * 8 + 2 * kq;
            int q_a = q0 + mt * 16 + r;
            int q_b = q_a + 8;
            *(__nv_bfloat162*)(g_attn + (size_t)q_a * H + col) =
                __floats2bfloat162_rn(accO[mt][nt][0] * inv[mt][0], accO[mt][nt][1] * inv[mt][0]);
            *(__nv_bfloat162*)(g_attn + (size_t)q_b * H + col) =
                __floats2bfloat162_rn(accO[mt][nt][2] * inv[mt][1], accO[mt][nt][3] * inv[mt][1]);
        }
}

// ---------------- launch -----------------------------------------------------
extern "C" void kernel_launch(void* const* d_in, const int* in_sizes, int n_in,
                              void* d_out, int out_size) {
    const float* x          = (const float*)d_in[0];
    const float* scale      = (const float*)d_in[1];
    const float* sinks      = (const float*)d_in[2];
    const float* qkv_kernel = (const float*)d_in[3];
    const float* qkv_bias   = (const float*)d_in[4];
    const float* out_kernel = (const float*)d_in[5];
    const float* out_bias   = (const float*)d_in[6];
    const float* cosb       = (const float*)d_in[7];
    const float* sinb       = (const float*)d_in[8];
    float* out = (float*)d_out;

    __nv_bfloat16 *pact, *pattn, *pqw, *pow;
    float* pq;
    cudaGetSymbolAddress((void**)&pact, g_act);
    cudaGetSymbolAddress((void**)&pq, g_qkv);
    cudaGetSymbolAddress((void**)&pattn, g_attn);
    cudaGetSymbolAddress((void**)&pqw, g_qkvw_t);
    cudaGetSymbolAddress((void**)&pow, g_outw_t);

    cudaFuncSetAttribute(attn_tc_kernel, cudaFuncAttributeMaxDynamicSharedMemorySize, ATT_SMEM);
    cudaFuncSetAttribute(gemm_tc_kernel, cudaFuncAttributeMaxDynamicSharedMemorySize, GEMM_SMEM);

    int prep_grid = T + (QKV_N / 32) * (H / 32) + (H / 32) * (H / 32);  // 12288
    prep_kernel<<<prep_grid, 256>>>(x, scale, qkv_kernel, out_kernel);
    gemm_tc_kernel<<<dim3(QKV_N / BN, T / BM), 256, GEMM_SMEM>>>(pact, pqw, qkv_bias, nullptr, pq, QKV_N, H);
    attn_tc_kernel<<<dim3(T / QT, NKV), 128, ATT_SMEM>>>(sinks, cosb, sinb);
    gemm_tc_kernel<<<dim3(H / BN, T / BM), 256, GEMM_SMEM>>>(pattn, pow, out_bias, x, out, H, H);
}

// round 13
// speedup vs baseline: 1.5346x; 1.5346x over previous
#include <cuda_runtime.h>
#include <cuda_bf16.h>
#include <cstdint>
#include <math.h>

#define T 2048
#define H 2048
#define QKV_N 3072
#define NH 32
#define NKV 8
#define QM 4
#define HD 64
#define SW 128
#define QT 32
#define MAXK (SW + QT)   // 160 keys max per query tile

// ---- GEMM tiling (mma.sync bf16): CTA 128x128, 8 warps of 64x32, BK=64 ----
#define BM 128
#define BN 128
#define BK 64
#define RS 144                      // padded smem row stride in bytes (128B data + 16B pad)
#define STAGE_A (128 * RS)          // 18432 B
#define STAGE (2 * STAGE_A)         // 36864 B
#define NSTAGE 2
#define GEMM_SMEM (NSTAGE * STAGE)  // 73728 B -> 2 CTAs/SM

// ---- attention smem (32-bit words): K + V + P only (Q staged thru P) ----
#define KSTR 68
#define VSTR 72
#define PSTR 36
#define ATT_K_W (MAXK * KSTR)             // 10880
#define ATT_V_W (MAXK * VSTR)             // 11520
#define ATT_P_W (4 * 32 * PSTR)           // 4608
#define ATT_SMEM ((ATT_K_W + ATT_V_W + ATT_P_W) * 4)  // 108032 B -> 2 CTAs/SM

// ---------------- scratch (device globals; no allocation allowed) ----------
__device__ __nv_bfloat16 g_act[(size_t)T * H];          // rmsnorm output (bf16)
__device__ float        g_qkv[(size_t)T * QKV_N];       // qkv output (fp32, pre-rope)
__device__ __nv_bfloat16 g_attn[(size_t)T * H];         // attention output (bf16)
__device__ __nv_bfloat16 g_qkvw_t[(size_t)QKV_N * H];   // qkv weight [N,K] bf16
__device__ __nv_bfloat16 g_outw_t[(size_t)H * H];       // out weight [N,K] bf16

// ---------------- helpers ----------------------------------------------
__device__ __forceinline__ uint32_t smem_u32(const void* p) {
    uint32_t a;
    asm("{ .reg .u64 t; cvta.to.shared.u64 t, %1; cvt.u32.u64 %0, t; }" : "=r"(a) : "l"(p));
    return a;
}
__device__ __forceinline__ void cp_async16(uint32_t saddr, const void* gaddr) {
    asm volatile("cp.async.cg.shared.global [%0], [%1], 16;" :: "r"(saddr), "l"(gaddr));
}
__device__ __forceinline__ void ldsm4(uint32_t* r, uint32_t a) {
    asm volatile("ldmatrix.sync.aligned.m8n8.x4.shared.b16 {%0,%1,%2,%3}, [%4];"
        : "=r"(r[0]), "=r"(r[1]), "=r"(r[2]), "=r"(r[3]) : "r"(a));
}
__device__ __forceinline__ void mma16816(float* c, const uint32_t* a, const uint32_t* b) {
    asm volatile("mma.sync.aligned.m16n8k16.row.col.f32.bf16.bf16.f32 "
        "{%0,%1,%2,%3}, {%4,%5,%6,%7}, {%8,%9}, {%0,%1,%2,%3};"
        : "+f"(c[0]), "+f"(c[1]), "+f"(c[2]), "+f"(c[3])
        : "r"(a[0]), "r"(a[1]), "r"(a[2]), "r"(a[3]), "r"(b[0]), "r"(b[1]));
}
__device__ __forceinline__ void mma_tf32(float* c, const uint32_t* a, const uint32_t* b) {
    asm volatile("mma.sync.aligned.m16n8k8.row.col.f32.tf32.tf32.f32 "
        "{%0,%1,%2,%3}, {%4,%5,%6,%7}, {%8,%9}, {%0,%1,%2,%3};"
        : "+f"(c[0]), "+f"(c[1]), "+f"(c[2]), "+f"(c[3])
        : "r"(a[0]), "r"(a[1]), "r"(a[2]), "r"(a[3]), "r"(b[0]), "r"(b[1]));
}
__device__ __forceinline__ uint32_t f2tf32(float f) {
    uint32_t u;
    asm("cvt.rna.tf32.f32 %0, %1;" : "=r"(u) : "f"(f));
    return u;
}
// exp(x) without MUFU: 2^t with t = x*log2(e), |frac| <= 0.5, degree-5 poly.
__device__ __forceinline__ float fast_exp(float x) {
    float t = x * 1.4426950408889634f;
    int i = __float2int_rn(t);
    float f = t - (float)i;
    float p = 1.3333558146e-3f;
    p = fmaf(p, f, 9.6181291076e-3f);
    p = fmaf(p, f, 5.5504108664e-2f);
    p = fmaf(p, f, 2.4022650696e-1f);
    p = fmaf(p, f, 6.9314718056e-1f);
    p = fmaf(p, f, 1.0f);
    float sc = __int_as_float((i + 127) << 23);
    return p * sc;
}

// ---------------- fused prep: rmsnorm + both weight transposes --------------
__device__ __forceinline__ void transpose_body(const float* __restrict__ S,
                                               __nv_bfloat16* __restrict__ D,
                                               int K, int N, int n0, int k0) {
    __shared__ float t[32][33];
    int tx = threadIdx.x & 31, ty = threadIdx.x >> 5;
    #pragma unroll
    for (int i = 0; i < 32; i += 8)
        t[ty + i][tx] = S[(size_t)(k0 + ty + i) * N + n0 + tx];
    __syncthreads();
    #pragma unroll
    for (int i = 0; i < 32; i += 8)
        D[(size_t)(n0 + ty + i) * K + k0 + tx] = __float2bfloat16(t[tx][ty + i]);
}

__global__ __launch_bounds__(256) void prep_kernel(const float* __restrict__ x,
                                                   const float* __restrict__ scale,
                                                   const float* __restrict__ qkvw,
                                                   const float* __restrict__ outw) {
    int b = blockIdx.x;
    if (b < T) {
        int row = b;
        const float4* xr4 = (const float4*)(x + (size_t)row * H);
        int tid = threadIdx.x;
        float4 v0 = xr4[tid], v1 = xr4[tid + 256];
        float ss = v0.x * v0.x + v0.y * v0.y + v0.z * v0.z + v0.w * v0.w
                 + v1.x * v1.x + v1.y * v1.y + v1.z * v1.z + v1.w * v1.w;
        for (int o = 16; o > 0; o >>= 1) ss += __shfl_xor_sync(0xffffffffu, ss, o);
        __shared__ float red[8];
        int wid = tid >> 5, lane = tid & 31;
        if (lane == 0) red[wid] = ss;
        __syncthreads();
        __shared__ float s_inv;
        if (tid == 0) {
            float t = 0.f;
            #pragma unroll
            for (int i = 0; i < 8; i++) t += red[i];
            s_inv = rsqrtf(t * (1.0f / (float)H) + 1e-5f);
        }
        __syncthreads();
        float inv = s_inv;
        const float4* sc4 = (const float4*)scale;
        float4 s0 = sc4[tid], s1 = sc4[tid + 256];
        __nv_bfloat162* o2 = (__nv_bfloat162*)(g_act + (size_t)row * H);
        o2[2 * tid]     = __floats2bfloat162_rn(v0.x * inv * s0.x, v0.y * inv * s0.y);
        o2[2 * tid + 1] = __floats2bfloat162_rn(v0.z * inv * s0.z, v0.w * inv * s0.w);
        o2[2 * (tid + 256)]     = __floats2bfloat162_rn(v1.x * inv * s1.x, v1.y * inv * s1.y);
        o2[2 * (tid + 256) + 1] = __floats2bfloat162_rn(v1.z * inv * s1.z, v1.w * inv * s1.w);
    } else if (b < T + (QKV_N / 32) * (H / 32)) {
        int bx = b - T;
        transpose_body(qkvw, g_qkvw_t, H, QKV_N, (bx % (QKV_N / 32)) * 32, (bx / (QKV_N / 32)) * 32);
    } else {
        int bx = b - T - (QKV_N / 32) * (H / 32);
        transpose_body(outw, g_outw_t, H, H, (bx % (H / 32)) * 32, (bx / (H / 32)) * 32);
    }
}

// ---------------- bf16 mma.sync GEMM: C = A[M,K] @ Bt[N,K]^T + bias (+resid)
// CTA 128x128x64, 8 warps (2x4) of 64x32, double-buffered cp.async, 2 CTAs/SM.
__global__ __launch_bounds__(256) void gemm_tc_kernel(const __nv_bfloat16* __restrict__ A,
                                                      const __nv_bfloat16* __restrict__ Bt,
                                                      const float* __restrict__ bias,
                                                      const float* __restrict__ resid,
                                                      float* __restrict__ C,
                                                      int N, int K) {
    extern __shared__ char smem[];
    uint32_t sbase = smem_u32(smem);

    int tid = threadIdx.x;
    int wid = tid >> 5, lane = tid & 31;
    int wm = wid & 1;
    int wn = wid >> 1;
    int bm = blockIdx.y * BM, bn = blockIdx.x * BN;

    float acc[4][4][4];
    #pragma unroll
    for (int i = 0; i < 4; i++)
        #pragma unroll
        for (int j = 0; j < 4; j++)
            #pragma unroll
            for (int e = 0; e < 4; e++) acc[i][j][e] = 0.f;

    const int nk = K / BK;   // 32

    // stage loader: A[128][64] + B[128][64] bf16 (128B rows, padded to 144B)
    auto load_stage = [&](int it) {
        uint32_t sb = sbase + (it & 1) * STAGE;
        const __nv_bfloat16* Ag = A + (size_t)bm * K + it * BK;
        const __nv_bfloat16* Bg = Bt + (size_t)bn * K + it * BK;
        #pragma unroll
        for (int i = 0; i < 4; i++) {
            int c = tid + i * 256;
            int row = c >> 3, h = c & 7;
            cp_async16(sb + row * RS + h * 16, Ag + (size_t)row * K + h * 8);
        }
        #pragma unroll
        for (int i = 0; i < 4; i++) {
            int c = tid + i * 256;
            int row = c >> 3, h = c & 7;
            cp_async16(sb + STAGE_A + row * RS + h * 16, Bg + (size_t)row * K + h * 8);
        }
        asm volatile("cp.async.commit_group;" ::: "memory");
    };

    load_stage(0);

    uint32_t aoff = (uint32_t)(lane & 15) * RS + (uint32_t)(lane >> 4) * 16;
    uint32_t boff = (uint32_t)(wn * 32 + ((lane >> 4) << 3) + (lane & 7)) * RS
                  + (uint32_t)((lane >> 3) & 1) * 16;

    auto mma4 = [&](int mi, const uint32_t* a, const uint32_t* b0, const uint32_t* b1) {
        mma16816(acc[mi][0], a, b0);
        mma16816(acc[mi][1], a, b0 + 2);
        mma16816(acc[mi][2], a, b1);
        mma16816(acc[mi][3], a, b1 + 2);
    };

    for (int it = 0; it < nk; it++) {
        asm volatile("cp.async.wait_group 0;" ::: "memory");
        __syncthreads();
        // prefetch the other buffer (consumed last iter; all warps past it via the sync)
        if (it + 1 < nk) load_stage(it + 1);

        uint32_t sb = sbase + (it & 1) * STAGE;
        uint32_t aBase = sb + (uint32_t)(wm * 64) * RS + aoff;
        uint32_t bBase = sb + STAGE_A + boff;

        // two halves of BK=64; each half = the R10 rolling fragment schedule
        #pragma unroll
        for (int h = 0; h < 2; h++) {
            uint32_t o0 = h * 64, o1 = h * 64 + 32;
            uint32_t bA0[4], bA1[4], bB0[4], bB1[4], aP[4], aQ[4];
            ldsm4(bA0, bBase + o0);
            ldsm4(bA1, bBase + (uint32_t)(16 * RS) + o0);
            ldsm4(aP, aBase + o0);

            ldsm4(aQ, aBase + (uint32_t)(16 * RS) + o0);
            mma4(0, aP, bA0, bA1);

            ldsm4(aP, aBase + (uint32_t)(32 * RS) + o0);
            mma4(1, aQ, bA0, bA1);

            ldsm4(aQ, aBase + (uint32_t)(48 * RS) + o0);
            ldsm4(bB0, bBase + o1);
            mma4(2, aP, bA0, bA1);

            ldsm4(bB1, bBase + (uint32_t)(16 * RS) + o1);
            ldsm4(aP, aBase + o1);
            mma4(3, aQ, bA0, bA1);

            ldsm4(aQ, aBase + (uint32_t)(16 * RS) + o1);
            mma4(0, aP, bB0, bB1);

            ldsm4(aP, aBase + (uint32_t)(32 * RS) + o1);
            mma4(1, aQ, bB0, bB1);

            ldsm4(aQ, aBase + (uint32_t)(48 * RS) + o1);
            mma4(2, aP, bB0, bB1);

            mma4(3, aQ, bB0, bB1);
        }
    }

    int rq = lane >> 2, cq = (lane & 3) * 2;
    #pragma unroll
    for (int mi = 0; mi < 4; mi++) {
        int r0 = bm + wm * 64 + mi * 16 + rq;
        #pragma unroll
        for (int half = 0; half < 2; half++) {
            int r = r0 + half * 8;
            float* crow = C + (size_t)r * N;
            const float* rrow = resid ? resid + (size_t)r * N : (const float*)0;
            #pragma unroll
            for (int nj = 0; nj < 4; nj++) {
                int c = bn + wn * 32 + nj * 8 + cq;
                float2 v;
                v.x = acc[mi][nj][half * 2 + 0] + bias[c];
                v.y = acc[mi][nj][half * 2 + 1] + bias[c + 1];
                if (rrow) { v.x += rrow[c]; v.y += rrow[c + 1]; }
                *(float2*)&crow[c] = v;
            }
        }
    }
}

// ---------------- tensor-core windowed GQA attention (rope fused) -----------
__global__ __launch_bounds__(128, 2) void attn_tc_kernel(const float* __restrict__ sinks,
                                                         const float* __restrict__ cosb,
                                                         const float* __restrict__ sinb) {
    extern __shared__ uint32_t shu[];
    uint32_t* Ku = shu;                       // [160][KSTR]
    uint32_t* Vu = Ku + ATT_K_W;              // [160][VSTR]
    uint32_t* Pu = Vu + ATT_V_W;              // [4][32][PSTR]

    int nkv = blockIdx.y;
    int q0 = blockIdx.x * QT;
    int ks = q0 - SW; if (ks < 0) ks = 0;
    int nk = q0 + QT - ks;                    // multiple of 32
    int nchunk = nk >> 5;

    int tid = threadIdx.x, w = tid >> 5, lane = tid & 31;

    const float* kbase = g_qkv + H + nkv * HD;
    for (int idx = tid; idx < nk * 8; idx += 128) {
        int c = idx & 7;
        int row = idx >> 3;
        int t = ks + row;
        const float* base = kbase + (size_t)t * QKV_N;
        float4 lo = *(const float4*)(base + c * 4);
        float4 hi = *(const float4*)(base + 32 + c * 4);
        float4 cs = *(const float4*)(cosb + t * 32 + c * 4);
        float4 sn = *(const float4*)(sinb + t * 32 + c * 4);
        uint32_t* dst = Ku + row * KSTR + c * 4;
        dst[0] = f2tf32(lo.x * cs.x - hi.x * sn.x);
        dst[1] = f2tf32(lo.y * cs.y - hi.y * sn.y);
        dst[2] = f2tf32(lo.z * cs.z - hi.z * sn.z);
        dst[3] = f2tf32(lo.w * cs.w - hi.w * sn.w);
        dst[32] = f2tf32(hi.x * cs.x + lo.x * sn.x);
        dst[33] = f2tf32(hi.y * cs.y + lo.y * sn.y);
        dst[34] = f2tf32(hi.z * cs.z + lo.z * sn.z);
        dst[35] = f2tf32(hi.w * cs.w + lo.w * sn.w);
    }
    const float* vbase = g_qkv + H + NKV * HD + nkv * HD;
    for (int idx = tid; idx < nk * 16; idx += 128) {
        int r0 = idx >> 4, c4 = (idx & 15) << 2;
        float4 v = *(const float4*)(vbase + (size_t)(ks + r0) * QKV_N + c4);
        uint32_t* dst = Vu + r0 * VSTR + c4;
        dst[0] = f2tf32(v.x); dst[1] = f2tf32(v.y);
        dst[2] = f2tf32(v.z); dst[3] = f2tf32(v.w);
    }
    __syncthreads();

    int r = lane >> 2, kq = lane & 3;
    uint32_t* Pw = Pu + w * 32 * PSTR;

    // per-warp Q staging through own P slab: rope + scale + tf32, two halves
    uint32_t af[2][8][4];
    {
        int row = lane;
        int tq = q0 + row;
        const float* qbase = g_qkv + (size_t)tq * QKV_N + (nkv * QM + w) * HD;
        #pragma unroll
        for (int h = 0; h < 2; h++) {
            #pragma unroll
            for (int c4 = 0; c4 < 8; c4++) {
                float4 lo = *(const float4*)(qbase + c4 * 4);
                float4 hi = *(const float4*)(qbase + 32 + c4 * 4);
                float4 cs = *(const float4*)(cosb + tq * 32 + c4 * 4);
                float4 sn = *(const float4*)(sinb + tq * 32 + c4 * 4);
                uint4 o;
                if (h == 0) {
                    o.x = f2tf32((lo.x * cs.x - hi.x * sn.x) * 0.125f);
                    o.y = f2tf32((lo.y * cs.y - hi.y * sn.y) * 0.125f);
                    o.z = f2tf32((lo.z * cs.z - hi.z * sn.z) * 0.125f);
                    o.w = f2tf32((lo.w * cs.w - hi.w * sn.w) * 0.125f);
                } else {
                    o.x = f2tf32((hi.x * cs.x + lo.x * sn.x) * 0.125f);
                    o.y = f2tf32((hi.y * cs.y + lo.y * sn.y) * 0.125f);
                    o.z = f2tf32((hi.z * cs.z + lo.z * sn.z) * 0.125f);
                    o.w = f2tf32((hi.w * cs.w + lo.w * sn.w) * 0.125f);
                }
                *(uint4*)&Pw[row * PSTR + c4 * 4] = o;
            }
            __syncwarp();
            #pragma unroll
            for (int mt = 0; mt < 2; mt++)
                #pragma unroll
                for (int kt2 = 0; kt2 < 4; kt2++) {
                    int kt = h * 4 + kt2;
                    af[mt][kt][0] = Pw[(mt * 16 + r) * PSTR + kt2 * 8 + kq];
                    af[mt][kt][1] = Pw[(mt * 16 + r + 8) * PSTR + kt2 * 8 + kq];
                    af[mt][kt][2] = Pw[(mt * 16 + r) * PSTR + kt2 * 8 + kq + 4];
                    af[mt][kt][3] = Pw[(mt * 16 + r + 8) * PSTR + kt2 * 8 + kq + 4];
                }
            __syncwarp();
        }
    }

    float accO[2][8][4];
    #pragma unroll
    for (int mt = 0; mt < 2; mt++)
        #pragma unroll
        for (int nt = 0; nt < 8; nt++)
            #pragma unroll
            for (int e = 0; e < 4; e++) accO[mt][nt][e] = 0.f;
    float lsum[2][2] = {{0.f, 0.f}, {0.f, 0.f}};

    for (int c = 0; c < nchunk; c++) {
        float S[2][4][4];
        #pragma unroll
        for (int mt = 0; mt < 2; mt++)
            #pragma unroll
            for (int nt = 0; nt < 4; nt++)
                #pragma unroll
                for (int e = 0; e < 4; e++) S[mt][nt][e] = 0.f;
        #pragma unroll
        for (int nt = 0; nt < 4; nt++) {
            int key = c * 32 + nt * 8 + r;
            #pragma unroll
            for (int kt = 0; kt < 8; kt++) {
                uint32_t b[2];
                b[0] = Ku[key * KSTR + kt * 8 + kq];
                b[1] = Ku[key * KSTR + kt * 8 + kq + 4];
                mma_tf32(S[0][nt], af[0][kt], b);
                mma_tf32(S[1][nt], af[1][kt], b);
            }
        }
        #pragma unroll
        for (int mt = 0; mt < 2; mt++)
            #pragma unroll
            for (int nt = 0; nt < 4; nt++) {
                #pragma unroll
                for (int e = 0; e < 4; e++) {
                    int half = e >> 1;
                    int q = q0 + mt * 16 + r + half * 8;
                    int kp = ks + c * 32 + nt * 8 + 2 * kq + (e & 1);
                    float p = fast_exp(S[mt][nt][e]);
                    p = (kp <= q && q - kp <= SW) ? p : 0.f;
                    lsum[mt][half] += p;
                    S[mt][nt][e] = p;
                }
                *(uint2*)&Pw[(mt * 16 + r) * PSTR + nt * 8 + 2 * kq] =
                    make_uint2(f2tf32(S[mt][nt][0]), f2tf32(S[mt][nt][1]));
                *(uint2*)&Pw[(mt * 16 + r + 8) * PSTR + nt * 8 + 2 * kq] =
                    make_uint2(f2tf32(S[mt][nt][2]), f2tf32(S[mt][nt][3]));
            }
        __syncwarp();
        #pragma unroll
        for (int kt = 0; kt < 4; kt++) {
            uint32_t pa[2][4];
            #pragma unroll
            for (int mt = 0; mt < 2; mt++) {
                pa[mt][0] = Pw[(mt * 16 + r) * PSTR + kt * 8 + kq];
                pa[mt][1] = Pw[(mt * 16 + r + 8) * PSTR + kt * 8 + kq];
                pa[mt][2] = Pw[(mt * 16 + r) * PSTR + kt * 8 + kq + 4];
                pa[mt][3] = Pw[(mt * 16 + r + 8) * PSTR + kt * 8 + kq + 4];
            }
            int key = c * 32 + kt * 8;
            #pragma unroll
            for (int nt = 0; nt < 8; nt++) {
                uint32_t b[2];
                b[0] = Vu[(key + kq) * VSTR + nt * 8 + r];
                b[1] = Vu[(key + kq + 4) * VSTR + nt * 8 + r];
                mma_tf32(accO[0][nt], pa[0], b);
                mma_tf32(accO[1][nt], pa[1], b);
            }
        }
        __syncwarp();
    }

    float sk = fast_exp(sinks[nkv * QM + w]);
    float inv[2][2];
    #pragma unroll
    for (int mt = 0; mt < 2; mt++)
        #pragma unroll
        for (int half = 0; half < 2; half++) {
            float l = lsum[mt][half];
            l += __shfl_xor_sync(0xffffffffu, l, 1);
            l += __shfl_xor_sync(0xffffffffu, l, 2);
            inv[mt][half] = 1.f / (l + sk);
        }

    int headcol = (nkv * QM + w) * HD;
    #pragma unroll
    for (int mt = 0; mt < 2; mt++)
        #pragma unroll
        for (int nt = 0; nt < 8; nt++) {
            int col = headcol + nt * 8 + 2 * kq;
            int q_a = q0 + mt * 16 + r;
            int q_b = q_a + 8;
            *(__nv_bfloat162*)(g_attn + (size_t)q_a * H + col) =
                __floats2bfloat162_rn(accO[mt][nt][0] * inv[mt][0], accO[mt][nt][1] * inv[mt][0]);
            *(__nv_bfloat162*)(g_attn + (size_t)q_b * H + col) =
                __floats2bfloat162_rn(accO[mt][nt][2] * inv[mt][1], accO[mt][nt][3] * inv[mt][1]);
        }
}

// ---------------- launch -----------------------------------------------------
extern "C" void kernel_launch(void* const* d_in, const int* in_sizes, int n_in,
                              void* d_out, int out_size) {
    const float* x          = (const float*)d_in[0];
    const float* scale      = (const float*)d_in[1];
    const float* sinks      = (const float*)d_in[2];
    const float* qkv_kernel = (const float*)d_in[3];
    const float* qkv_bias   = (const float*)d_in[4];
    const float* out_kernel = (const float*)d_in[5];
    const float* out_bias   = (const float*)d_in[6];
    const float* cosb       = (const float*)d_in[7];
    const float* sinb       = (const float*)d_in[8];
    float* out = (float*)d_out;

    __nv_bfloat16 *pact, *pattn, *pqw, *pow;
    float* pq;
    cudaGetSymbolAddress((void**)&pact, g_act);
    cudaGetSymbolAddress((void**)&pq, g_qkv);
    cudaGetSymbolAddress((void**)&pattn, g_attn);
    cudaGetSymbolAddress((void**)&pqw, g_qkvw_t);
    cudaGetSymbolAddress((void**)&pow, g_outw_t);

    cudaFuncSetAttribute(attn_tc_kernel, cudaFuncAttributeMaxDynamicSharedMemorySize, ATT_SMEM);
    cudaFuncSetAttribute(gemm_tc_kernel, cudaFuncAttributeMaxDynamicSharedMemorySize, GEMM_SMEM);

    int prep_grid = T + (QKV_N / 32) * (H / 32) + (H / 32) * (H / 32);  // 12288
    prep_kernel<<<prep_grid, 256>>>(x, scale, qkv_kernel, out_kernel);
    gemm_tc_kernel<<<dim3(QKV_N / BN, T / BM), 256, GEMM_SMEM>>>(pact, pqw, qkv_bias, nullptr, pq, QKV_N, H);
    attn_tc_kernel<<<dim3(T / QT, NKV), 128, ATT_SMEM>>>(sinks, cosb, sinb);
    gemm_tc_kernel<<<dim3(H / BN, T / BM), 256, GEMM_SMEM>>>(pattn, pow, out_bias, x, out, H, H);
}

// round 14
// speedup vs baseline: 1.5498x; 1.0099x over previous
#include <cuda_runtime.h>
#include <cuda_bf16.h>
#include <cstdint>
#include <math.h>

#define T 2048
#define H 2048
#define QKV_N 3072
#define NH 32
#define NKV 8
#define QM 4
#define HD 64
#define SW 128
#define QT 32
#define MAXK (SW + QT)   // 160 keys max per query tile

// ---- GEMM tiling (mma.sync bf16): CTA 128x128, 8 warps of 64x32, BK=64 ----
#define BM 128
#define BN 128
#define BK 64
#define RS 144                      // padded smem row stride in bytes (128B data + 16B pad)
#define STAGE_A (128 * RS)          // 18432 B
#define STAGE (2 * STAGE_A)         // 36864 B
#define NSTAGE 2
#define GEMM_SMEM (NSTAGE * STAGE)  // 73728 B -> 2 CTAs/SM

// ---- attention smem (32-bit words): K + V + P only (Q staged thru P) ----
#define KSTR 68
#define VSTR 72
#define PSTR 36
#define ATT_K_W (MAXK * KSTR)             // 10880
#define ATT_V_W (MAXK * VSTR)             // 11520
#define ATT_P_W (4 * 32 * PSTR)           // 4608
#define ATT_SMEM ((ATT_K_W + ATT_V_W + ATT_P_W) * 4)  // 108032 B -> 2 CTAs/SM

// softmax scale with log2(e) folded in: p = exp2(s * QSCALE) == exp(s * 0.125)
#define QSCALE (0.125f * 1.44269504088896340736f)

// ---------------- scratch (device globals; no allocation allowed) ----------
__device__ __nv_bfloat16 g_act[(size_t)T * H];          // rmsnorm output (bf16)
__device__ float        g_qkv[(size_t)T * QKV_N];       // qkv output (fp32, pre-rope)
__device__ __nv_bfloat16 g_attn[(size_t)T * H];         // attention output (bf16)
__device__ __nv_bfloat16 g_qkvw_t[(size_t)QKV_N * H];   // qkv weight [N,K] bf16
__device__ __nv_bfloat16 g_outw_t[(size_t)H * H];       // out weight [N,K] bf16

// ---------------- helpers ----------------------------------------------
__device__ __forceinline__ uint32_t smem_u32(const void* p) {
    uint32_t a;
    asm("{ .reg .u64 t; cvta.to.shared.u64 t, %1; cvt.u32.u64 %0, t; }" : "=r"(a) : "l"(p));
    return a;
}
__device__ __forceinline__ void cp_async16(uint32_t saddr, const void* gaddr) {
    asm volatile("cp.async.cg.shared.global [%0], [%1], 16;" :: "r"(saddr), "l"(gaddr));
}
__device__ __forceinline__ void ldsm4(uint32_t* r, uint32_t a) {
    asm volatile("ldmatrix.sync.aligned.m8n8.x4.shared.b16 {%0,%1,%2,%3}, [%4];"
        : "=r"(r[0]), "=r"(r[1]), "=r"(r[2]), "=r"(r[3]) : "r"(a));
}
__device__ __forceinline__ void mma16816(float* c, const uint32_t* a, const uint32_t* b) {
    asm volatile("mma.sync.aligned.m16n8k16.row.col.f32.bf16.bf16.f32 "
        "{%0,%1,%2,%3}, {%4,%5,%6,%7}, {%8,%9}, {%0,%1,%2,%3};"
        : "+f"(c[0]), "+f"(c[1]), "+f"(c[2]), "+f"(c[3])
        : "r"(a[0]), "r"(a[1]), "r"(a[2]), "r"(a[3]), "r"(b[0]), "r"(b[1]));
}
__device__ __forceinline__ void mma_tf32(float* c, const uint32_t* a, const uint32_t* b) {
    asm volatile("mma.sync.aligned.m16n8k8.row.col.f32.tf32.tf32.f32 "
        "{%0,%1,%2,%3}, {%4,%5,%6,%7}, {%8,%9}, {%0,%1,%2,%3};"
        : "+f"(c[0]), "+f"(c[1]), "+f"(c[2]), "+f"(c[3])
        : "r"(a[0]), "r"(a[1]), "r"(a[2]), "r"(a[3]), "r"(b[0]), "r"(b[1]));
}
__device__ __forceinline__ uint32_t f2tf32(float f) {
    uint32_t u;
    asm("cvt.rna.tf32.f32 %0, %1;" : "=r"(u) : "f"(f));
    return u;
}

// ---------------- fused prep: rmsnorm + both weight transposes --------------
__device__ __forceinline__ void transpose_body(const float* __restrict__ S,
                                               __nv_bfloat16* __restrict__ D,
                                               int K, int N, int n0, int k0) {
    __shared__ float t[32][33];
    int tx = threadIdx.x & 31, ty = threadIdx.x >> 5;
    #pragma unroll
    for (int i = 0; i < 32; i += 8)
        t[ty + i][tx] = S[(size_t)(k0 + ty + i) * N + n0 + tx];
    __syncthreads();
    #pragma unroll
    for (int i = 0; i < 32; i += 8)
        D[(size_t)(n0 + ty + i) * K + k0 + tx] = __float2bfloat16(t[tx][ty + i]);
}

__global__ __launch_bounds__(256) void prep_kernel(const float* __restrict__ x,
                                                   const float* __restrict__ scale,
                                                   const float* __restrict__ qkvw,
                                                   const float* __restrict__ outw) {
    int b = blockIdx.x;
    if (b < T) {
        int row = b;
        const float4* xr4 = (const float4*)(x + (size_t)row * H);
        int tid = threadIdx.x;
        float4 v0 = xr4[tid], v1 = xr4[tid + 256];
        float ss = v0.x * v0.x + v0.y * v0.y + v0.z * v0.z + v0.w * v0.w
                 + v1.x * v1.x + v1.y * v1.y + v1.z * v1.z + v1.w * v1.w;
        for (int o = 16; o > 0; o >>= 1) ss += __shfl_xor_sync(0xffffffffu, ss, o);
        __shared__ float red[8];
        int wid = tid >> 5, lane = tid & 31;
        if (lane == 0) red[wid] = ss;
        __syncthreads();
        __shared__ float s_inv;
        if (tid == 0) {
            float t = 0.f;
            #pragma unroll
            for (int i = 0; i < 8; i++) t += red[i];
            s_inv = rsqrtf(t * (1.0f / (float)H) + 1e-5f);
        }
        __syncthreads();
        float inv = s_inv;
        const float4* sc4 = (const float4*)scale;
        float4 s0 = sc4[tid], s1 = sc4[tid + 256];
        __nv_bfloat162* o2 = (__nv_bfloat162*)(g_act + (size_t)row * H);
        o2[2 * tid]     = __floats2bfloat162_rn(v0.x * inv * s0.x, v0.y * inv * s0.y);
        o2[2 * tid + 1] = __floats2bfloat162_rn(v0.z * inv * s0.z, v0.w * inv * s0.w);
        o2[2 * (tid + 256)]     = __floats2bfloat162_rn(v1.x * inv * s1.x, v1.y * inv * s1.y);
        o2[2 * (tid + 256) + 1] = __floats2bfloat162_rn(v1.z * inv * s1.z, v1.w * inv * s1.w);
    } else if (b < T + (QKV_N / 32) * (H / 32)) {
        int bx = b - T;
        transpose_body(qkvw, g_qkvw_t, H, QKV_N, (bx % (QKV_N / 32)) * 32, (bx / (QKV_N / 32)) * 32);
    } else {
        int bx = b - T - (QKV_N / 32) * (H / 32);
        transpose_body(outw, g_outw_t, H, H, (bx % (H / 32)) * 32, (bx / (H / 32)) * 32);
    }
}

// ---------------- bf16 mma.sync GEMM: C = A[M,K] @ Bt[N,K]^T + bias (+resid)
// CTA 128x128x64, 8 warps (2x4) of 64x32, double-buffered cp.async, 2 CTAs/SM.
__global__ __launch_bounds__(256) void gemm_tc_kernel(const __nv_bfloat16* __restrict__ A,
                                                      const __nv_bfloat16* __restrict__ Bt,
                                                      const float* __restrict__ bias,
                                                      const float* __restrict__ resid,
                                                      float* __restrict__ C,
                                                      int N, int K) {
    extern __shared__ char smem[];
    uint32_t sbase = smem_u32(smem);

    int tid = threadIdx.x;
    int wid = tid >> 5, lane = tid & 31;
    int wm = wid & 1;
    int wn = wid >> 1;
    int bm = blockIdx.y * BM, bn = blockIdx.x * BN;

    float acc[4][4][4];
    #pragma unroll
    for (int i = 0; i < 4; i++)
        #pragma unroll
        for (int j = 0; j < 4; j++)
            #pragma unroll
            for (int e = 0; e < 4; e++) acc[i][j][e] = 0.f;

    const int nk = K / BK;

    auto load_stage = [&](int it) {
        uint32_t sb = sbase + (it & 1) * STAGE;
        const __nv_bfloat16* Ag = A + (size_t)bm * K + it * BK;
        const __nv_bfloat16* Bg = Bt + (size_t)bn * K + it * BK;
        #pragma unroll
        for (int i = 0; i < 4; i++) {
            int c = tid + i * 256;
            int row = c >> 3, h = c & 7;
            cp_async16(sb + row * RS + h * 16, Ag + (size_t)row * K + h * 8);
        }
        #pragma unroll
        for (int i = 0; i < 4; i++) {
            int c = tid + i * 256;
            int row = c >> 3, h = c & 7;
            cp_async16(sb + STAGE_A + row * RS + h * 16, Bg + (size_t)row * K + h * 8);
        }
        asm volatile("cp.async.commit_group;" ::: "memory");
    };

    load_stage(0);

    uint32_t aoff = (uint32_t)(lane & 15) * RS + (uint32_t)(lane >> 4) * 16;
    uint32_t boff = (uint32_t)(wn * 32 + ((lane >> 4) << 3) + (lane & 7)) * RS
                  + (uint32_t)((lane >> 3) & 1) * 16;

    auto mma4 = [&](int mi, const uint32_t* a, const uint32_t* b0, const uint32_t* b1) {
        mma16816(acc[mi][0], a, b0);
        mma16816(acc[mi][1], a, b0 + 2);
        mma16816(acc[mi][2], a, b1);
        mma16816(acc[mi][3], a, b1 + 2);
    };

    for (int it = 0; it < nk; it++) {
        asm volatile("cp.async.wait_group 0;" ::: "memory");
        __syncthreads();
        if (it + 1 < nk) load_stage(it + 1);

        uint32_t sb = sbase + (it & 1) * STAGE;
        uint32_t aBase = sb + (uint32_t)(wm * 64) * RS + aoff;
        uint32_t bBase = sb + STAGE_A + boff;

        #pragma unroll
        for (int h = 0; h < 2; h++) {
            uint32_t o0 = h * 64, o1 = h * 64 + 32;
            uint32_t bA0[4], bA1[4], bB0[4], bB1[4], aP[4], aQ[4];
            ldsm4(bA0, bBase + o0);
            ldsm4(bA1, bBase + (uint32_t)(16 * RS) + o0);
            ldsm4(aP, aBase + o0);

            ldsm4(aQ, aBase + (uint32_t)(16 * RS) + o0);
            mma4(0, aP, bA0, bA1);

            ldsm4(aP, aBase + (uint32_t)(32 * RS) + o0);
            mma4(1, aQ, bA0, bA1);

            ldsm4(aQ, aBase + (uint32_t)(48 * RS) + o0);
            ldsm4(bB0, bBase + o1);
            mma4(2, aP, bA0, bA1);

            ldsm4(bB1, bBase + (uint32_t)(16 * RS) + o1);
            ldsm4(aP, aBase + o1);
            mma4(3, aQ, bA0, bA1);

            ldsm4(aQ, aBase + (uint32_t)(16 * RS) + o1);
            mma4(0, aP, bB0, bB1);

            ldsm4(aP, aBase + (uint32_t)(32 * RS) + o1);
            mma4(1, aQ, bB0, bB1);

            ldsm4(aQ, aBase + (uint32_t)(48 * RS) + o1);
            mma4(2, aP, bB0, bB1);

            mma4(3, aQ, bB0, bB1);
        }
    }

    int rq = lane >> 2, cq = (lane & 3) * 2;
    #pragma unroll
    for (int mi = 0; mi < 4; mi++) {
        int r0 = bm + wm * 64 + mi * 16 + rq;
        #pragma unroll
        for (int half = 0; half < 2; half++) {
            int r = r0 + half * 8;
            float* crow = C + (size_t)r * N;
            const float* rrow = resid ? resid + (size_t)r * N : (const float*)0;
            #pragma unroll
            for (int nj = 0; nj < 4; nj++) {
                int c = bn + wn * 32 + nj * 8 + cq;
                float2 v;
                v.x = acc[mi][nj][half * 2 + 0] + bias[c];
                v.y = acc[mi][nj][half * 2 + 1] + bias[c + 1];
                if (rrow) { v.x += rrow[c]; v.y += rrow[c + 1]; }
                *(float2*)&crow[c] = v;
            }
        }
    }
}

// ---------------- tensor-core windowed GQA attention (rope fused) -----------
// p = exp2(S) with log2(e) folded into the Q scale at staging; EX2 on MUFU.
__global__ __launch_bounds__(128, 2) void attn_tc_kernel(const float* __restrict__ sinks,
                                                         const float* __restrict__ cosb,
                                                         const float* __restrict__ sinb) {
    extern __shared__ uint32_t shu[];
    uint32_t* Ku = shu;                       // [160][KSTR]
    uint32_t* Vu = Ku + ATT_K_W;              // [160][VSTR]
    uint32_t* Pu = Vu + ATT_V_W;              // [4][32][PSTR]

    int nkv = blockIdx.y;
    int q0 = blockIdx.x * QT;
    int ks = q0 - SW; if (ks < 0) ks = 0;
    int nk = q0 + QT - ks;                    // multiple of 32
    int nchunk = nk >> 5;

    int tid = threadIdx.x, w = tid >> 5, lane = tid & 31;

    const float* kbase = g_qkv + H + nkv * HD;
    for (int idx = tid; idx < nk * 8; idx += 128) {
        int c = idx & 7;
        int row = idx >> 3;
        int t = ks + row;
        const float* base = kbase + (size_t)t * QKV_N;
        float4 lo = *(const float4*)(base + c * 4);
        float4 hi = *(const float4*)(base + 32 + c * 4);
        float4 cs = *(const float4*)(cosb + t * 32 + c * 4);
        float4 sn = *(const float4*)(sinb + t * 32 + c * 4);
        uint32_t* dst = Ku + row * KSTR + c * 4;
        dst[0] = f2tf32(lo.x * cs.x - hi.x * sn.x);
        dst[1] = f2tf32(lo.y * cs.y - hi.y * sn.y);
        dst[2] = f2tf32(lo.z * cs.z - hi.z * sn.z);
        dst[3] = f2tf32(lo.w * cs.w - hi.w * sn.w);
        dst[32] = f2tf32(hi.x * cs.x + lo.x * sn.x);
        dst[33] = f2tf32(hi.y * cs.y + lo.y * sn.y);
        dst[34] = f2tf32(hi.z * cs.z + lo.z * sn.z);
        dst[35] = f2tf32(hi.w * cs.w + lo.w * sn.w);
    }
    const float* vbase = g_qkv + H + NKV * HD + nkv * HD;
    for (int idx = tid; idx < nk * 16; idx += 128) {
        int r0 = idx >> 4, c4 = (idx & 15) << 2;
        float4 v = *(const float4*)(vbase + (size_t)(ks + r0) * QKV_N + c4);
        uint32_t* dst = Vu + r0 * VSTR + c4;
        dst[0] = f2tf32(v.x); dst[1] = f2tf32(v.y);
        dst[2] = f2tf32(v.z); dst[3] = f2tf32(v.w);
    }
    __syncthreads();

    int r = lane >> 2, kq = lane & 3;
    uint32_t* Pw = Pu + w * 32 * PSTR;

    // per-warp Q staging through own P slab: rope + scale(incl log2e) + tf32
    uint32_t af[2][8][4];
    {
        int row = lane;
        int tq = q0 + row;
        const float* qbase = g_qkv + (size_t)tq * QKV_N + (nkv * QM + w) * HD;
        #pragma unroll
        for (int h = 0; h < 2; h++) {
            #pragma unroll
            for (int c4 = 0; c4 < 8; c4++) {
                float4 lo = *(const float4*)(qbase + c4 * 4);
                float4 hi = *(const float4*)(qbase + 32 + c4 * 4);
                float4 cs = *(const float4*)(cosb + tq * 32 + c4 * 4);
                float4 sn = *(const float4*)(sinb + tq * 32 + c4 * 4);
                uint4 o;
                if (h == 0) {
                    o.x = f2tf32((lo.x * cs.x - hi.x * sn.x) * QSCALE);
                    o.y = f2tf32((lo.y * cs.y - hi.y * sn.y) * QSCALE);
                    o.z = f2tf32((lo.z * cs.z - hi.z * sn.z) * QSCALE);
                    o.w = f2tf32((lo.w * cs.w - hi.w * sn.w) * QSCALE);
                } else {
                    o.x = f2tf32((hi.x * cs.x + lo.x * sn.x) * QSCALE);
                    o.y = f2tf32((hi.y * cs.y + lo.y * sn.y) * QSCALE);
                    o.z = f2tf32((hi.z * cs.z + lo.z * sn.z) * QSCALE);
                    o.w = f2tf32((hi.w * cs.w + lo.w * sn.w) * QSCALE);
                }
                *(uint4*)&Pw[row * PSTR + c4 * 4] = o;
            }
            __syncwarp();
            #pragma unroll
            for (int mt = 0; mt < 2; mt++)
                #pragma unroll
                for (int kt2 = 0; kt2 < 4; kt2++) {
                    int kt = h * 4 + kt2;
                    af[mt][kt][0] = Pw[(mt * 16 + r) * PSTR + kt2 * 8 + kq];
                    af[mt][kt][1] = Pw[(mt * 16 + r + 8) * PSTR + kt2 * 8 + kq];
                    af[mt][kt][2] = Pw[(mt * 16 + r) * PSTR + kt2 * 8 + kq + 4];
                    af[mt][kt][3] = Pw[(mt * 16 + r + 8) * PSTR + kt2 * 8 + kq + 4];
                }
            __syncwarp();
        }
    }

    float accO[2][8][4];
    #pragma unroll
    for (int mt = 0; mt < 2; mt++)
        #pragma unroll
        for (int nt = 0; nt < 8; nt++)
            #pragma unroll
            for (int e = 0; e < 4; e++) accO[mt][nt][e] = 0.f;
    float lsum[2][2] = {{0.f, 0.f}, {0.f, 0.f}};

    for (int c = 0; c < nchunk; c++) {
        float S[2][4][4];
        #pragma unroll
        for (int mt = 0; mt < 2; mt++)
            #pragma unroll
            for (int nt = 0; nt < 4; nt++)
                #pragma unroll
                for (int e = 0; e < 4; e++) S[mt][nt][e] = 0.f;
        #pragma unroll
        for (int nt = 0; nt < 4; nt++) {
            int key = c * 32 + nt * 8 + r;
            #pragma unroll
            for (int kt = 0; kt < 8; kt++) {
                uint32_t b[2];
                b[0] = Ku[key * KSTR + kt * 8 + kq];
                b[1] = Ku[key * KSTR + kt * 8 + kq + 4];
                mma_tf32(S[0][nt], af[0][kt], b);
                mma_tf32(S[1][nt], af[1][kt], b);
            }
        }
        #pragma unroll
        for (int mt = 0; mt < 2; mt++)
            #pragma unroll
            for (int nt = 0; nt < 4; nt++) {
                #pragma unroll
                for (int e = 0; e < 4; e++) {
                    int half = e >> 1;
                    int q = q0 + mt * 16 + r + half * 8;
                    int kp = ks + c * 32 + nt * 8 + 2 * kq + (e & 1);
                    float p = exp2f(S[mt][nt][e]);              // single EX2
                    p = ((unsigned)(q - kp) <= (unsigned)SW) ? p : 0.f;
                    lsum[mt][half] += p;
                    S[mt][nt][e] = p;
                }
                *(uint2*)&Pw[(mt * 16 + r) * PSTR + nt * 8 + 2 * kq] =
                    make_uint2(f2tf32(S[mt][nt][0]), f2tf32(S[mt][nt][1]));
                *(uint2*)&Pw[(mt * 16 + r + 8) * PSTR + nt * 8 + 2 * kq] =
                    make_uint2(f2tf32(S[mt][nt][2]), f2tf32(S[mt][nt][3]));
            }
        __syncwarp();
        #pragma unroll
        for (int kt = 0; kt < 4; kt++) {
            uint32_t pa[2][4];
            #pragma unroll
            for (int mt = 0; mt < 2; mt++) {
                pa[mt][0] = Pw[(mt * 16 + r) * PSTR + kt * 8 + kq];
                pa[mt][1] = Pw[(mt * 16 + r + 8) * PSTR + kt * 8 + kq];
                pa[mt][2] = Pw[(mt * 16 + r) * PSTR + kt * 8 + kq + 4];
                pa[mt][3] = Pw[(mt * 16 + r + 8) * PSTR + kt * 8 + kq + 4];
            }
            int key = c * 32 + kt * 8;
            #pragma unroll
            for (int nt = 0; nt < 8; nt++) {
                uint32_t b[2];
                b[0] = Vu[(key + kq) * VSTR + nt * 8 + r];
                b[1] = Vu[(key + kq + 4) * VSTR + nt * 8 + r];
                mma_tf32(accO[0][nt], pa[0], b);
                mma_tf32(accO[1][nt], pa[1], b);
            }
        }
        __syncwarp();
    }

    float sk = exp2f(sinks[nkv * QM + w] * 1.44269504088896340736f);
    float inv[2][2];
    #pragma unroll
    for (int mt = 0; mt < 2; mt++)
        #pragma unroll
        for (int half = 0; half < 2; half++) {
            float l = lsum[mt][half];
            l += __shfl_xor_sync(0xffffffffu, l, 1);
            l += __shfl_xor_sync(0xffffffffu, l, 2);
            inv[mt][half] = 1.f / (l + sk);
        }

    int headcol = (nkv * QM + w) * HD;
    #pragma unroll
    for (int mt = 0; mt < 2; mt++)
        #pragma unroll
        for (int nt = 0; nt < 8; nt++) {
            int col = headcol + nt * 8 + 2 * kq;
            int q_a = q0 + mt * 16 + r;
            int q_b = q_a + 8;
            *(__nv_bfloat162*)(g_attn + (size_t)q_a * H + col) =
                __floats2bfloat162_rn(accO[mt][nt][0] * inv[mt][0], accO[mt][nt][1] * inv[mt][0]);
            *(__nv_bfloat162*)(g_attn + (size_t)q_b * H + col) =
                __floats2bfloat162_rn(accO[mt][nt][2] * inv[mt][1], accO[mt][nt][3] * inv[mt][1]);
        }
}

// ---------------- launch -----------------------------------------------------
extern "C" void kernel_launch(void* const* d_in, const int* in_sizes, int n_in,
                              void* d_out, int out_size) {
    const float* x          = (const float*)d_in[0];
    const float* scale      = (const float*)d_in[1];
    const float* sinks      = (const float*)d_in[2];
    const float* qkv_kernel = (const float*)d_in[3];
    const float* qkv_bias   = (const float*)d_in[4];
    const float* out_kernel = (const float*)d_in[5];
    const float* out_bias   = (const float*)d_in[6];
    const float* cosb       = (const float*)d_in[7];
    const float* sinb       = (const float*)d_in[8];
    float* out = (float*)d_out;

    __nv_bfloat16 *pact, *pattn, *pqw, *pow;
    float* pq;
    cudaGetSymbolAddress((void**)&pact, g_act);
    cudaGetSymbolAddress((void**)&pq, g_qkv);
    cudaGetSymbolAddress((void**)&pattn, g_attn);
    cudaGetSymbolAddress((void**)&pqw, g_qkvw_t);
    cudaGetSymbolAddress((void**)&pow, g_outw_t);

    cudaFuncSetAttribute(attn_tc_kernel, cudaFuncAttributeMaxDynamicSharedMemorySize, ATT_SMEM);
    cudaFuncSetAttribute(gemm_tc_kernel, cudaFuncAttributeMaxDynamicSharedMemorySize, GEMM_SMEM);

    int prep_grid = T + (QKV_N / 32) * (H / 32) + (H / 32) * (H / 32);  // 12288
    prep_kernel<<<prep_grid, 256>>>(x, scale, qkv_kernel, out_kernel);
    gemm_tc_kernel<<<dim3(QKV_N / BN, T / BM), 256, GEMM_SMEM>>>(pact, pqw, qkv_bias, nullptr, pq, QKV_N, H);
    attn_tc_kernel<<<dim3(T / QT, NKV), 128, ATT_SMEM>>>(sinks, cosb, sinb);
    gemm_tc_kernel<<<dim3(H / BN, T / BM), 256, GEMM_SMEM>>>(pattn, pow, out_bias, x, out, H, H);
}

// round 15
// speedup vs baseline: 1.5643x; 1.0094x over previous
#include <cuda_runtime.h>
#include <cuda_bf16.h>
#include <cstdint>
#include <math.h>

#define T 2048
#define H 2048
#define QKV_N 3072
#define NH 32
#define NKV 8
#define QM 4
#define HD 64
#define SW 128
#define QT 64
#define MAXK (SW + QT)   // 192 keys max per query tile

// ---- GEMM tiling (mma.sync bf16): CTA 128x128, 8 warps of 64x32, BK=64 ----
#define BM 128
#define BN 128
#define BK 64
#define RS 144                      // padded smem row stride in bytes (128B data + 16B pad)
#define STAGE_A (128 * RS)          // 18432 B
#define STAGE (2 * STAGE_A)         // 36864 B
#define NSTAGE 2
#define GEMM_SMEM (NSTAGE * STAGE)  // 73728 B -> 2 CTAs/SM

// ---- attention smem (32-bit words): K + V + 8 P slabs ----
#define KSTR 68
#define VSTR 72
#define PSTR 36
#define ATT_K_W (MAXK * KSTR)             // 13056
#define ATT_V_W (MAXK * VSTR)             // 13824
#define ATT_P_W (8 * 32 * PSTR)           // 9216
#define ATT_SMEM ((ATT_K_W + ATT_V_W + ATT_P_W) * 4)  // 144384 B -> 1 CTA/SM (8 warps)

// softmax scale with log2(e) folded in: p = exp2(s * QSCALE) == exp(s * 0.125)
#define QSCALE (0.125f * 1.44269504088896340736f)

// ---------------- scratch (device globals; no allocation allowed) ----------
__device__ __nv_bfloat16 g_act[(size_t)T * H];          // rmsnorm output (bf16)
__device__ float        g_qkv[(size_t)T * QKV_N];       // qkv output (fp32, pre-rope)
__device__ __nv_bfloat16 g_attn[(size_t)T * H];         // attention output (bf16)
__device__ __nv_bfloat16 g_qkvw_t[(size_t)QKV_N * H];   // qkv weight [N,K] bf16
__device__ __nv_bfloat16 g_outw_t[(size_t)H * H];       // out weight [N,K] bf16

// ---------------- helpers ----------------------------------------------
__device__ __forceinline__ uint32_t smem_u32(const void* p) {
    uint32_t a;
    asm("{ .reg .u64 t; cvta.to.shared.u64 t, %1; cvt.u32.u64 %0, t; }" : "=r"(a) : "l"(p));
    return a;
}
__device__ __forceinline__ void cp_async16(uint32_t saddr, const void* gaddr) {
    asm volatile("cp.async.cg.shared.global [%0], [%1], 16;" :: "r"(saddr), "l"(gaddr));
}
__device__ __forceinline__ void ldsm4(uint32_t* r, uint32_t a) {
    asm volatile("ldmatrix.sync.aligned.m8n8.x4.shared.b16 {%0,%1,%2,%3}, [%4];"
        : "=r"(r[0]), "=r"(r[1]), "=r"(r[2]), "=r"(r[3]) : "r"(a));
}
__device__ __forceinline__ void mma16816(float* c, const uint32_t* a, const uint32_t* b) {
    asm volatile("mma.sync.aligned.m16n8k16.row.col.f32.bf16.bf16.f32 "
        "{%0,%1,%2,%3}, {%4,%5,%6,%7}, {%8,%9}, {%0,%1,%2,%3};"
        : "+f"(c[0]), "+f"(c[1]), "+f"(c[2]), "+f"(c[3])
        : "r"(a[0]), "r"(a[1]), "r"(a[2]), "r"(a[3]), "r"(b[0]), "r"(b[1]));
}
__device__ __forceinline__ void mma_tf32(float* c, const uint32_t* a, const uint32_t* b) {
    asm volatile("mma.sync.aligned.m16n8k8.row.col.f32.tf32.tf32.f32 "
        "{%0,%1,%2,%3}, {%4,%5,%6,%7}, {%8,%9}, {%0,%1,%2,%3};"
        : "+f"(c[0]), "+f"(c[1]), "+f"(c[2]), "+f"(c[3])
        : "r"(a[0]), "r"(a[1]), "r"(a[2]), "r"(a[3]), "r"(b[0]), "r"(b[1]));
}
__device__ __forceinline__ uint32_t f2tf32(float f) {
    uint32_t u;
    asm("cvt.rna.tf32.f32 %0, %1;" : "=r"(u) : "f"(f));
    return u;
}

// ---------------- fused prep: rmsnorm + both weight transposes --------------
__device__ __forceinline__ void transpose_body(const float* __restrict__ S,
                                               __nv_bfloat16* __restrict__ D,
                                               int K, int N, int n0, int k0) {
    __shared__ float t[32][33];
    int tx = threadIdx.x & 31, ty = threadIdx.x >> 5;
    #pragma unroll
    for (int i = 0; i < 32; i += 8)
        t[ty + i][tx] = S[(size_t)(k0 + ty + i) * N + n0 + tx];
    __syncthreads();
    #pragma unroll
    for (int i = 0; i < 32; i += 8)
        D[(size_t)(n0 + ty + i) * K + k0 + tx] = __float2bfloat16(t[tx][ty + i]);
}

__global__ __launch_bounds__(256) void prep_kernel(const float* __restrict__ x,
                                                   const float* __restrict__ scale,
                                                   const float* __restrict__ qkvw,
                                                   const float* __restrict__ outw) {
    int b = blockIdx.x;
    if (b < T) {
        int row = b;
        const float4* xr4 = (const float4*)(x + (size_t)row * H);
        int tid = threadIdx.x;
        float4 v0 = xr4[tid], v1 = xr4[tid + 256];
        float ss = v0.x * v0.x + v0.y * v0.y + v0.z * v0.z + v0.w * v0.w
                 + v1.x * v1.x + v1.y * v1.y + v1.z * v1.z + v1.w * v1.w;
        for (int o = 16; o > 0; o >>= 1) ss += __shfl_xor_sync(0xffffffffu, ss, o);
        __shared__ float red[8];
        int wid = tid >> 5, lane = tid & 31;
        if (lane == 0) red[wid] = ss;
        __syncthreads();
        __shared__ float s_inv;
        if (tid == 0) {
            float t = 0.f;
            #pragma unroll
            for (int i = 0; i < 8; i++) t += red[i];
            s_inv = rsqrtf(t * (1.0f / (float)H) + 1e-5f);
        }
        __syncthreads();
        float inv = s_inv;
        const float4* sc4 = (const float4*)scale;
        float4 s0 = sc4[tid], s1 = sc4[tid + 256];
        __nv_bfloat162* o2 = (__nv_bfloat162*)(g_act + (size_t)row * H);
        o2[2 * tid]     = __floats2bfloat162_rn(v0.x * inv * s0.x, v0.y * inv * s0.y);
        o2[2 * tid + 1] = __floats2bfloat162_rn(v0.z * inv * s0.z, v0.w * inv * s0.w);
        o2[2 * (tid + 256)]     = __floats2bfloat162_rn(v1.x * inv * s1.x, v1.y * inv * s1.y);
        o2[2 * (tid + 256) + 1] = __floats2bfloat162_rn(v1.z * inv * s1.z, v1.w * inv * s1.w);
    } else if (b < T + (QKV_N / 32) * (H / 32)) {
        int bx = b - T;
        transpose_body(qkvw, g_qkvw_t, H, QKV_N, (bx % (QKV_N / 32)) * 32, (bx / (QKV_N / 32)) * 32);
    } else {
        int bx = b - T - (QKV_N / 32) * (H / 32);
        transpose_body(outw, g_outw_t, H, H, (bx % (H / 32)) * 32, (bx / (H / 32)) * 32);
    }
}

// ---------------- bf16 mma.sync GEMM: C = A[M,K] @ Bt[N,K]^T + bias (+resid)
// CTA 128x128x64, 8 warps (2x4) of 64x32, double-buffered cp.async, 2 CTAs/SM.
__global__ __launch_bounds__(256) void gemm_tc_kernel(const __nv_bfloat16* __restrict__ A,
                                                      const __nv_bfloat16* __restrict__ Bt,
                                                      const float* __restrict__ bias,
                                                      const float* __restrict__ resid,
                                                      float* __restrict__ C,
                                                      int N, int K) {
    extern __shared__ char smem[];
    uint32_t sbase = smem_u32(smem);

    int tid = threadIdx.x;
    int wid = tid >> 5, lane = tid & 31;
    int wm = wid & 1;
    int wn = wid >> 1;
    int bm = blockIdx.y * BM, bn = blockIdx.x * BN;

    float acc[4][4][4];
    #pragma unroll
    for (int i = 0; i < 4; i++)
        #pragma unroll
        for (int j = 0; j < 4; j++)
            #pragma unroll
            for (int e = 0; e < 4; e++) acc[i][j][e] = 0.f;

    const int nk = K / BK;

    auto load_stage = [&](int it) {
        uint32_t sb = sbase + (it & 1) * STAGE;
        const __nv_bfloat16* Ag = A + (size_t)bm * K + it * BK;
        const __nv_bfloat16* Bg = Bt + (size_t)bn * K + it * BK;
        #pragma unroll
        for (int i = 0; i < 4; i++) {
            int c = tid + i * 256;
            int row = c >> 3, h = c & 7;
            cp_async16(sb + row * RS + h * 16, Ag + (size_t)row * K + h * 8);
        }
        #pragma unroll
        for (int i = 0; i < 4; i++) {
            int c = tid + i * 256;
            int row = c >> 3, h = c & 7;
            cp_async16(sb + STAGE_A + row * RS + h * 16, Bg + (size_t)row * K + h * 8);
        }
        asm volatile("cp.async.commit_group;" ::: "memory");
    };

    load_stage(0);

    uint32_t aoff = (uint32_t)(lane & 15) * RS + (uint32_t)(lane >> 4) * 16;
    uint32_t boff = (uint32_t)(wn * 32 + ((lane >> 4) << 3) + (lane & 7)) * RS
                  + (uint32_t)((lane >> 3) & 1) * 16;

    auto mma4 = [&](int mi, const uint32_t* a, const uint32_t* b0, const uint32_t* b1) {
        mma16816(acc[mi][0], a, b0);
        mma16816(acc[mi][1], a, b0 + 2);
        mma16816(acc[mi][2], a, b1);
        mma16816(acc[mi][3], a, b1 + 2);
    };

    for (int it = 0; it < nk; it++) {
        asm volatile("cp.async.wait_group 0;" ::: "memory");
        __syncthreads();
        if (it + 1 < nk) load_stage(it + 1);

        uint32_t sb = sbase + (it & 1) * STAGE;
        uint32_t aBase = sb + (uint32_t)(wm * 64) * RS + aoff;
        uint32_t bBase = sb + STAGE_A + boff;

        #pragma unroll
        for (int h = 0; h < 2; h++) {
            uint32_t o0 = h * 64, o1 = h * 64 + 32;
            uint32_t bA0[4], bA1[4], bB0[4], bB1[4], aP[4], aQ[4];
            ldsm4(bA0, bBase + o0);
            ldsm4(bA1, bBase + (uint32_t)(16 * RS) + o0);
            ldsm4(aP, aBase + o0);

            ldsm4(aQ, aBase + (uint32_t)(16 * RS) + o0);
            mma4(0, aP, bA0, bA1);

            ldsm4(aP, aBase + (uint32_t)(32 * RS) + o0);
            mma4(1, aQ, bA0, bA1);

            ldsm4(aQ, aBase + (uint32_t)(48 * RS) + o0);
            ldsm4(bB0, bBase + o1);
            mma4(2, aP, bA0, bA1);

            ldsm4(bB1, bBase + (uint32_t)(16 * RS) + o1);
            ldsm4(aP, aBase + o1);
            mma4(3, aQ, bA0, bA1);

            ldsm4(aQ, aBase + (uint32_t)(16 * RS) + o1);
            mma4(0, aP, bB0, bB1);

            ldsm4(aP, aBase + (uint32_t)(32 * RS) + o1);
            mma4(1, aQ, bB0, bB1);

            ldsm4(aQ, aBase + (uint32_t)(48 * RS) + o1);
            mma4(2, aP, bB0, bB1);

            mma4(3, aQ, bB0, bB1);
        }
    }

    int rq = lane >> 2, cq = (lane & 3) * 2;
    #pragma unroll
    for (int mi = 0; mi < 4; mi++) {
        int r0 = bm + wm * 64 + mi * 16 + rq;
        #pragma unroll
        for (int half = 0; half < 2; half++) {
            int r = r0 + half * 8;
            float* crow = C + (size_t)r * N;
            const float* rrow = resid ? resid + (size_t)r * N : (const float*)0;
            #pragma unroll
            for (int nj = 0; nj < 4; nj++) {
                int c = bn + wn * 32 + nj * 8 + cq;
                float2 v;
                v.x = acc[mi][nj][half * 2 + 0] + bias[c];
                v.y = acc[mi][nj][half * 2 + 1] + bias[c + 1];
                if (rrow) { v.x += rrow[c]; v.y += rrow[c + 1]; }
                *(float2*)&crow[c] = v;
            }
        }
    }
}

// ---------------- tensor-core windowed GQA attention (rope fused, QT=64) ----
// grid (T/64, NKV), 256 threads = 8 warps; warp w = (head w>>1, query-half w&1).
__global__ __launch_bounds__(256, 1) void attn_tc_kernel(const float* __restrict__ sinks,
                                                         const float* __restrict__ cosb,
                                                         const float* __restrict__ sinb) {
    extern __shared__ uint32_t shu[];
    uint32_t* Ku = shu;                       // [192][KSTR]
    uint32_t* Vu = Ku + ATT_K_W;              // [192][VSTR]
    uint32_t* Pu = Vu + ATT_V_W;              // [8][32][PSTR]

    int nkv = blockIdx.y;
    int q0 = blockIdx.x * QT;
    int ks = q0 - SW; if (ks < 0) ks = 0;
    int nk = q0 + QT - ks;                    // 64, 128, or 192 (multiple of 32)
    int nchunk = nk >> 5;

    int tid = threadIdx.x, w = tid >> 5, lane = tid & 31;
    int head = w >> 1, qh = w & 1;

    // stage K: rope + tf32 (block cooperative, 256 threads)
    const float* kbase = g_qkv + H + nkv * HD;
    for (int idx = tid; idx < nk * 8; idx += 256) {
        int c = idx & 7;
        int row = idx >> 3;
        int t = ks + row;
        const float* base = kbase + (size_t)t * QKV_N;
        float4 lo = *(const float4*)(base + c * 4);
        float4 hi = *(const float4*)(base + 32 + c * 4);
        float4 cs = *(const float4*)(cosb + t * 32 + c * 4);
        float4 sn = *(const float4*)(sinb + t * 32 + c * 4);
        uint32_t* dst = Ku + row * KSTR + c * 4;
        dst[0] = f2tf32(lo.x * cs.x - hi.x * sn.x);
        dst[1] = f2tf32(lo.y * cs.y - hi.y * sn.y);
        dst[2] = f2tf32(lo.z * cs.z - hi.z * sn.z);
        dst[3] = f2tf32(lo.w * cs.w - hi.w * sn.w);
        dst[32] = f2tf32(hi.x * cs.x + lo.x * sn.x);
        dst[33] = f2tf32(hi.y * cs.y + lo.y * sn.y);
        dst[34] = f2tf32(hi.z * cs.z + lo.z * sn.z);
        dst[35] = f2tf32(hi.w * cs.w + lo.w * sn.w);
    }
    // stage V: tf32
    const float* vbase = g_qkv + H + NKV * HD + nkv * HD;
    for (int idx = tid; idx < nk * 16; idx += 256) {
        int r0 = idx >> 4, c4 = (idx & 15) << 2;
        float4 v = *(const float4*)(vbase + (size_t)(ks + r0) * QKV_N + c4);
        uint32_t* dst = Vu + r0 * VSTR + c4;
        dst[0] = f2tf32(v.x); dst[1] = f2tf32(v.y);
        dst[2] = f2tf32(v.z); dst[3] = f2tf32(v.w);
    }
    __syncthreads();

    int r = lane >> 2, kq = lane & 3;
    uint32_t* Pw = Pu + w * 32 * PSTR;

    // per-warp Q staging through own P slab: rope + scale(incl log2e) + tf32
    uint32_t af[2][8][4];
    {
        int tq = q0 + qh * 32 + lane;
        const float* qbase = g_qkv + (size_t)tq * QKV_N + (nkv * QM + head) * HD;
        #pragma unroll
        for (int h = 0; h < 2; h++) {
            #pragma unroll
            for (int c4 = 0; c4 < 8; c4++) {
                float4 lo = *(const float4*)(qbase + c4 * 4);
                float4 hi = *(const float4*)(qbase + 32 + c4 * 4);
                float4 cs = *(const float4*)(cosb + tq * 32 + c4 * 4);
                float4 sn = *(const float4*)(sinb + tq * 32 + c4 * 4);
                uint4 o;
                if (h == 0) {
                    o.x = f2tf32((lo.x * cs.x - hi.x * sn.x) * QSCALE);
                    o.y = f2tf32((lo.y * cs.y - hi.y * sn.y) * QSCALE);
                    o.z = f2tf32((lo.z * cs.z - hi.z * sn.z) * QSCALE);
                    o.w = f2tf32((lo.w * cs.w - hi.w * sn.w) * QSCALE);
                } else {
                    o.x = f2tf32((hi.x * cs.x + lo.x * sn.x) * QSCALE);
                    o.y = f2tf32((hi.y * cs.y + lo.y * sn.y) * QSCALE);
                    o.z = f2tf32((hi.z * cs.z + lo.z * sn.z) * QSCALE);
                    o.w = f2tf32((hi.w * cs.w + lo.w * sn.w) * QSCALE);
                }
                *(uint4*)&Pw[lane * PSTR + c4 * 4] = o;
            }
            __syncwarp();
            #pragma unroll
            for (int mt = 0; mt < 2; mt++)
                #pragma unroll
                for (int kt2 = 0; kt2 < 4; kt2++) {
                    int kt = h * 4 + kt2;
                    af[mt][kt][0] = Pw[(mt * 16 + r) * PSTR + kt2 * 8 + kq];
                    af[mt][kt][1] = Pw[(mt * 16 + r + 8) * PSTR + kt2 * 8 + kq];
                    af[mt][kt][2] = Pw[(mt * 16 + r) * PSTR + kt2 * 8 + kq + 4];
                    af[mt][kt][3] = Pw[(mt * 16 + r + 8) * PSTR + kt2 * 8 + kq + 4];
                }
            __syncwarp();
        }
    }

    float accO[2][8][4];
    #pragma unroll
    for (int mt = 0; mt < 2; mt++)
        #pragma unroll
        for (int nt = 0; nt < 8; nt++)
            #pragma unroll
            for (int e = 0; e < 4; e++) accO[mt][nt][e] = 0.f;
    float lsum[2][2] = {{0.f, 0.f}, {0.f, 0.f}};

    for (int c = 0; c < nchunk; c++) {
        float S[2][4][4];
        #pragma unroll
        for (int mt = 0; mt < 2; mt++)
            #pragma unroll
            for (int nt = 0; nt < 4; nt++)
                #pragma unroll
                for (int e = 0; e < 4; e++) S[mt][nt][e] = 0.f;
        #pragma unroll
        for (int nt = 0; nt < 4; nt++) {
            int key = c * 32 + nt * 8 + r;
            #pragma unroll
            for (int kt = 0; kt < 8; kt++) {
                uint32_t b[2];
                b[0] = Ku[key * KSTR + kt * 8 + kq];
                b[1] = Ku[key * KSTR + kt * 8 + kq + 4];
                mma_tf32(S[0][nt], af[0][kt], b);
                mma_tf32(S[1][nt], af[1][kt], b);
            }
        }
        #pragma unroll
        for (int mt = 0; mt < 2; mt++)
            #pragma unroll
            for (int nt = 0; nt < 4; nt++) {
                #pragma unroll
                for (int e = 0; e < 4; e++) {
                    int half = e >> 1;
                    int q = q0 + qh * 32 + mt * 16 + r + half * 8;
                    int kp = ks + c * 32 + nt * 8 + 2 * kq + (e & 1);
                    float p = exp2f(S[mt][nt][e]);              // single EX2
                    p = ((unsigned)(q - kp) <= (unsigned)SW) ? p : 0.f;
                    lsum[mt][half] += p;
                    S[mt][nt][e] = p;
                }
                *(uint2*)&Pw[(mt * 16 + r) * PSTR + nt * 8 + 2 * kq] =
                    make_uint2(f2tf32(S[mt][nt][0]), f2tf32(S[mt][nt][1]));
                *(uint2*)&Pw[(mt * 16 + r + 8) * PSTR + nt * 8 + 2 * kq] =
                    make_uint2(f2tf32(S[mt][nt][2]), f2tf32(S[mt][nt][3]));
            }
        __syncwarp();
        #pragma unroll
        for (int kt = 0; kt < 4; kt++) {
            uint32_t pa[2][4];
            #pragma unroll
            for (int mt = 0; mt < 2; mt++) {
                pa[mt][0] = Pw[(mt * 16 + r) * PSTR + kt * 8 + kq];
                pa[mt][1] = Pw[(mt * 16 + r + 8) * PSTR + kt * 8 + kq];
                pa[mt][2] = Pw[(mt * 16 + r) * PSTR + kt * 8 + kq + 4];
                pa[mt][3] = Pw[(mt * 16 + r + 8) * PSTR + kt * 8 + kq + 4];
            }
            int key = c * 32 + kt * 8;
            #pragma unroll
            for (int nt = 0; nt < 8; nt++) {
                uint32_t b[2];
                b[0] = Vu[(key + kq) * VSTR + nt * 8 + r];
                b[1] = Vu[(key + kq + 4) * VSTR + nt * 8 + r];
                mma_tf32(accO[0][nt], pa[0], b);
                mma_tf32(accO[1][nt], pa[1], b);
            }
        }
        __syncwarp();
    }

    float sk = exp2f(sinks[nkv * QM + head] * 1.44269504088896340736f);
    float inv[2][2];
    #pragma unroll
    for (int mt = 0; mt < 2; mt++)
        #pragma unroll
        for (int half = 0; half < 2; half++) {
            float l = lsum[mt][half];
            l += __shfl_xor_sync(0xffffffffu, l, 1);
            l += __shfl_xor_sync(0xffffffffu, l, 2);
            inv[mt][half] = 1.f / (l + sk);
        }

    int headcol = (nkv * QM + head) * HD;
    #pragma unroll
    for (int mt = 0; mt < 2; mt++)
        #pragma unroll
        for (int nt = 0; nt < 8; nt++) {
            int col = headcol + nt * 8 + 2 * kq;
            int q_a = q0 + qh * 32 + mt * 16 + r;
            int q_b = q_a + 8;
            *(__nv_bfloat162*)(g_attn + (size_t)q_a * H + col) =
                __floats2bfloat162_rn(accO[mt][nt][0] * inv[mt][0], accO[mt][nt][1] * inv[mt][0]);
            *(__nv_bfloat162*)(g_attn + (size_t)q_b * H + col) =
                __floats2bfloat162_rn(accO[mt][nt][2] * inv[mt][1], accO[mt][nt][3] * inv[mt][1]);
        }
}

// ---------------- launch -----------------------------------------------------
extern "C" void kernel_launch(void* const* d_in, const int* in_sizes, int n_in,
                              void* d_out, int out_size) {
    const float* x          = (const float*)d_in[0];
    const float* scale      = (const float*)d_in[1];
    const float* sinks      = (const float*)d_in[2];
    const float* qkv_kernel = (const float*)d_in[3];
    const float* qkv_bias   = (const float*)d_in[4];
    const float* out_kernel = (const float*)d_in[5];
    const float* out_bias   = (const float*)d_in[6];
    const float* cosb       = (const float*)d_in[7];
    const float* sinb       = (const float*)d_in[8];
    float* out = (float*)d_out;

    __nv_bfloat16 *pact, *pattn, *pqw, *pow;
    float* pq;
    cudaGetSymbolAddress((void**)&pact, g_act);
    cudaGetSymbolAddress((void**)&pq, g_qkv);
    cudaGetSymbolAddress((void**)&pattn, g_attn);
    cudaGetSymbolAddress((void**)&pqw, g_qkvw_t);
    cudaGetSymbolAddress((void**)&pow, g_outw_t);

    cudaFuncSetAttribute(attn_tc_kernel, cudaFuncAttributeMaxDynamicSharedMemorySize, ATT_SMEM);
    cudaFuncSetAttribute(gemm_tc_kernel, cudaFuncAttributeMaxDynamicSharedMemorySize, GEMM_SMEM);

    int prep_grid = T + (QKV_N / 32) * (H / 32) + (H / 32) * (H / 32);  // 12288
    prep_kernel<<<prep_grid, 256>>>(x, scale, qkv_kernel, out_kernel);
    gemm_tc_kernel<<<dim3(QKV_N / BN, T / BM), 256, GEMM_SMEM>>>(pact, pqw, qkv_bias, nullptr, pq, QKV_N, H);
    attn_tc_kernel<<<dim3(T / QT, NKV), 256, ATT_SMEM>>>(sinks, cosb, sinb);
    gemm_tc_kernel<<<dim3(H / BN, T / BM), 256, GEMM_SMEM>>>(pattn, pow, out_bias, x, out, H, H);
}

// round 16
// speedup vs baseline: 1.6138x; 1.0317x over previous
#include <cuda_runtime.h>
#include <cuda_bf16.h>
#include <cuda_fp16.h>
#include <cstdint>
#include <math.h>

#define T 2048
#define H 2048
#define QKV_N 3072
#define NH 32
#define NKV 8
#define QM 4
#define HD 64
#define SW 128
#define QT 64
#define MAXK (SW + QT)   // 192 keys max per query tile

// ---- GEMM tiling (mma.sync bf16): CTA 128x128, 8 warps of 64x32, BK=64 ----
#define BM 128
#define BN 128
#define BK 64
#define RS 144                      // padded smem row stride in bytes
#define STAGE_A (128 * RS)          // 18432 B
#define STAGE (2 * STAGE_A)         // 36864 B
#define GEMM_SMEM (2 * STAGE)       // 73728 B -> 2 CTAs/SM

// ---- attention smem: K (tf32) + V (fp16) + 8 P slabs ----
#define KSTR 68                            // words per K row
#define VSTRH 72                           // halves per V row (144B; ldmatrix conflict-free)
#define PSTR 36                            // words per P-slab row (sized for Q staging)
#define ATT_K_W (MAXK * KSTR)              // 13056 words
#define ATT_V_W ((MAXK * VSTRH) / 2)       // 6912 words (fp16)
#define ATT_P_W (8 * 32 * PSTR)            // 9216 words
#define ATT_SMEM ((ATT_K_W + ATT_V_W + ATT_P_W) * 4)  // 116736 B

// softmax scale with log2(e) folded in: p = exp2(s * QSCALE) == exp(s * 0.125)
#define QSCALE (0.125f * 1.44269504088896340736f)

// ---------------- scratch (device globals; no allocation allowed) ----------
__device__ __nv_bfloat16 g_act[(size_t)T * H];
__device__ float        g_qkv[(size_t)T * QKV_N];
__device__ __nv_bfloat16 g_attn[(size_t)T * H];
__device__ __nv_bfloat16 g_qkvw_t[(size_t)QKV_N * H];
__device__ __nv_bfloat16 g_outw_t[(size_t)H * H];

// ---------------- helpers ----------------------------------------------
__device__ __forceinline__ uint32_t smem_u32(const void* p) {
    uint32_t a;
    asm("{ .reg .u64 t; cvta.to.shared.u64 t, %1; cvt.u32.u64 %0, t; }" : "=r"(a) : "l"(p));
    return a;
}
__device__ __forceinline__ void cp_async16(uint32_t saddr, const void* gaddr) {
    asm volatile("cp.async.cg.shared.global [%0], [%1], 16;" :: "r"(saddr), "l"(gaddr));
}
__device__ __forceinline__ void ldsm4(uint32_t* r, uint32_t a) {
    asm volatile("ldmatrix.sync.aligned.m8n8.x4.shared.b16 {%0,%1,%2,%3}, [%4];"
        : "=r"(r[0]), "=r"(r[1]), "=r"(r[2]), "=r"(r[3]) : "r"(a));
}
__device__ __forceinline__ void ldsm4t(uint32_t* r, uint32_t a) {
    asm volatile("ldmatrix.sync.aligned.m8n8.x4.trans.shared.b16 {%0,%1,%2,%3}, [%4];"
        : "=r"(r[0]), "=r"(r[1]), "=r"(r[2]), "=r"(r[3]) : "r"(a));
}
__device__ __forceinline__ void mma16816(float* c, const uint32_t* a, const uint32_t* b) {
    asm volatile("mma.sync.aligned.m16n8k16.row.col.f32.bf16.bf16.f32 "
        "{%0,%1,%2,%3}, {%4,%5,%6,%7}, {%8,%9}, {%0,%1,%2,%3};"
        : "+f"(c[0]), "+f"(c[1]), "+f"(c[2]), "+f"(c[3])
        : "r"(a[0]), "r"(a[1]), "r"(a[2]), "r"(a[3]), "r"(b[0]), "r"(b[1]));
}
__device__ __forceinline__ void mma_f16(float* c, const uint32_t* a, const uint32_t* b) {
    asm volatile("mma.sync.aligned.m16n8k16.row.col.f32.f16.f16.f32 "
        "{%0,%1,%2,%3}, {%4,%5,%6,%7}, {%8,%9}, {%0,%1,%2,%3};"
        : "+f"(c[0]), "+f"(c[1]), "+f"(c[2]), "+f"(c[3])
        : "r"(a[0]), "r"(a[1]), "r"(a[2]), "r"(a[3]), "r"(b[0]), "r"(b[1]));
}
__device__ __forceinline__ void mma_tf32(float* c, const uint32_t* a, const uint32_t* b) {
    asm volatile("mma.sync.aligned.m16n8k8.row.col.f32.tf32.tf32.f32 "
        "{%0,%1,%2,%3}, {%4,%5,%6,%7}, {%8,%9}, {%0,%1,%2,%3};"
        : "+f"(c[0]), "+f"(c[1]), "+f"(c[2]), "+f"(c[3])
        : "r"(a[0]), "r"(a[1]), "r"(a[2]), "r"(a[3]), "r"(b[0]), "r"(b[1]));
}
__device__ __forceinline__ uint32_t f2tf32(float f) {
    uint32_t u;
    asm("cvt.rna.tf32.f32 %0, %1;" : "=r"(u) : "f"(f));
    return u;
}

// ---------------- transpose tile: [K,N] f32 -> [N,K] bf16 -------------------
__device__ __forceinline__ void transpose_body(const float* __restrict__ S,
                                               __nv_bfloat16* __restrict__ D,
                                               int K, int N, int n0, int k0) {
    __shared__ float t[32][33];
    int tx = threadIdx.x & 31, ty = threadIdx.x >> 5;
    #pragma unroll
    for (int i = 0; i < 32; i += 8)
        t[ty + i][tx] = S[(size_t)(k0 + ty + i) * N + n0 + tx];
    __syncthreads();
    #pragma unroll
    for (int i = 0; i < 32; i += 8)
        D[(size_t)(n0 + ty + i) * K + k0 + tx] = __float2bfloat16(t[tx][ty + i]);
}

// ---------------- prep: rmsnorm + qkv weight transpose ----------------------
__global__ __launch_bounds__(256) void prep_kernel(const float* __restrict__ x,
                                                   const float* __restrict__ scale,
                                                   const float* __restrict__ qkvw) {
    int b = blockIdx.x;
    if (b < T) {
        int row = b;
        const float4* xr4 = (const float4*)(x + (size_t)row * H);
        int tid = threadIdx.x;
        float4 v0 = xr4[tid], v1 = xr4[tid + 256];
        float ss = v0.x * v0.x + v0.y * v0.y + v0.z * v0.z + v0.w * v0.w
                 + v1.x * v1.x + v1.y * v1.y + v1.z * v1.z + v1.w * v1.w;
        for (int o = 16; o > 0; o >>= 1) ss += __shfl_xor_sync(0xffffffffu, ss, o);
        __shared__ float red[8];
        int wid = tid >> 5, lane = tid & 31;
        if (lane == 0) red[wid] = ss;
        __syncthreads();
        __shared__ float s_inv;
        if (tid == 0) {
            float t = 0.f;
            #pragma unroll
            for (int i = 0; i < 8; i++) t += red[i];
            s_inv = rsqrtf(t * (1.0f / (float)H) + 1e-5f);
        }
        __syncthreads();
        float inv = s_inv;
        const float4* sc4 = (const float4*)scale;
        float4 s0 = sc4[tid], s1 = sc4[tid + 256];
        __nv_bfloat162* o2 = (__nv_bfloat162*)(g_act + (size_t)row * H);
        o2[2 * tid]     = __floats2bfloat162_rn(v0.x * inv * s0.x, v0.y * inv * s0.y);
        o2[2 * tid + 1] = __floats2bfloat162_rn(v0.z * inv * s0.z, v0.w * inv * s0.w);
        o2[2 * (tid + 256)]     = __floats2bfloat162_rn(v1.x * inv * s1.x, v1.y * inv * s1.y);
        o2[2 * (tid + 256) + 1] = __floats2bfloat162_rn(v1.z * inv * s1.z, v1.w * inv * s1.w);
    } else {
        int bx = b - T;   // 6144 qkvw tiles: 96 n-tiles x 64 k-tiles
        transpose_body(qkvw, g_qkvw_t, H, QKV_N, (bx % (QKV_N / 32)) * 32, (bx / (QKV_N / 32)) * 32);
    }
}

// ---------------- bf16 mma.sync GEMM (+ optional transpose tail CTAs) -------
// CTA 128x128x64, 8 warps (2x4) of 64x32, double-buffered cp.async, 2 CTAs/SM.
// blockIdx.y >= M/BM  => out-proj weight transpose tiles (overlaps GEMM tail).
__global__ __launch_bounds__(256) void gemm_tc_kernel(const __nv_bfloat16* __restrict__ A,
                                                      const __nv_bfloat16* __restrict__ Bt,
                                                      const float* __restrict__ bias,
                                                      const float* __restrict__ resid,
                                                      float* __restrict__ C,
                                                      int N, int K,
                                                      const float* __restrict__ tw_src,
                                                      __nv_bfloat16* __restrict__ tw_dst) {
    if (blockIdx.y >= (T / BM)) {
        int tb = ((blockIdx.y - T / BM) * gridDim.x + blockIdx.x) * 16;
        for (int i = 0; i < 16; i++) {
            int t = tb + i;
            if (t < (H / 32) * (H / 32))
                transpose_body(tw_src, tw_dst, H, H, (t & 63) * 32, (t >> 6) * 32);
            __syncthreads();
        }
        return;
    }

    extern __shared__ char smem[];
    uint32_t sbase = smem_u32(smem);

    int tid = threadIdx.x;
    int wid = tid >> 5, lane = tid & 31;
    int wm = wid & 1;
    int wn = wid >> 1;
    int bm = blockIdx.y * BM, bn = blockIdx.x * BN;

    float acc[4][4][4];
    #pragma unroll
    for (int i = 0; i < 4; i++)
        #pragma unroll
        for (int j = 0; j < 4; j++)
            #pragma unroll
            for (int e = 0; e < 4; e++) acc[i][j][e] = 0.f;

    const int nk = K / BK;

    auto load_stage = [&](int it) {
        uint32_t sb = sbase + (it & 1) * STAGE;
        const __nv_bfloat16* Ag = A + (size_t)bm * K + it * BK;
        const __nv_bfloat16* Bg = Bt + (size_t)bn * K + it * BK;
        #pragma unroll
        for (int i = 0; i < 4; i++) {
            int c = tid + i * 256;
            int row = c >> 3, h = c & 7;
            cp_async16(sb + row * RS + h * 16, Ag + (size_t)row * K + h * 8);
        }
        #pragma unroll
        for (int i = 0; i < 4; i++) {
            int c = tid + i * 256;
            int row = c >> 3, h = c & 7;
            cp_async16(sb + STAGE_A + row * RS + h * 16, Bg + (size_t)row * K + h * 8);
        }
        asm volatile("cp.async.commit_group;" ::: "memory");
    };

    load_stage(0);

    uint32_t aoff = (uint32_t)(lane & 15) * RS + (uint32_t)(lane >> 4) * 16;
    uint32_t boff = (uint32_t)(wn * 32 + ((lane >> 4) << 3) + (lane & 7)) * RS
                  + (uint32_t)((lane >> 3) & 1) * 16;

    auto mma4 = [&](int mi, const uint32_t* a, const uint32_t* b0, const uint32_t* b1) {
        mma16816(acc[mi][0], a, b0);
        mma16816(acc[mi][1], a, b0 + 2);
        mma16816(acc[mi][2], a, b1);
        mma16816(acc[mi][3], a, b1 + 2);
    };

    for (int it = 0; it < nk; it++) {
        asm volatile("cp.async.wait_group 0;" ::: "memory");
        __syncthreads();
        if (it + 1 < nk) load_stage(it + 1);

        uint32_t sb = sbase + (it & 1) * STAGE;
        uint32_t aBase = sb + (uint32_t)(wm * 64) * RS + aoff;
        uint32_t bBase = sb + STAGE_A + boff;

        #pragma unroll
        for (int h = 0; h < 2; h++) {
            uint32_t o0 = h * 64, o1 = h * 64 + 32;
            uint32_t bA0[4], bA1[4], bB0[4], bB1[4], aP[4], aQ[4];
            ldsm4(bA0, bBase + o0);
            ldsm4(bA1, bBase + (uint32_t)(16 * RS) + o0);
            ldsm4(aP, aBase + o0);

            ldsm4(aQ, aBase + (uint32_t)(16 * RS) + o0);
            mma4(0, aP, bA0, bA1);

            ldsm4(aP, aBase + (uint32_t)(32 * RS) + o0);
            mma4(1, aQ, bA0, bA1);

            ldsm4(aQ, aBase + (uint32_t)(48 * RS) + o0);
            ldsm4(bB0, bBase + o1);
            mma4(2, aP, bA0, bA1);

            ldsm4(bB1, bBase + (uint32_t)(16 * RS) + o1);
            ldsm4(aP, aBase + o1);
            mma4(3, aQ, bA0, bA1);

            ldsm4(aQ, aBase + (uint32_t)(16 * RS) + o1);
            mma4(0, aP, bB0, bB1);

            ldsm4(aP, aBase + (uint32_t)(32 * RS) + o1);
            mma4(1, aQ, bB0, bB1);

            ldsm4(aQ, aBase + (uint32_t)(48 * RS) + o1);
            mma4(2, aP, bB0, bB1);

            mma4(3, aQ, bB0, bB1);
        }
    }

    int rq = lane >> 2, cq = (lane & 3) * 2;
    #pragma unroll
    for (int mi = 0; mi < 4; mi++) {
        int r0 = bm + wm * 64 + mi * 16 + rq;
        #pragma unroll
        for (int half = 0; half < 2; half++) {
            int r = r0 + half * 8;
            float* crow = C + (size_t)r * N;
            const float* rrow = resid ? resid + (size_t)r * N : (const float*)0;
            #pragma unroll
            for (int nj = 0; nj < 4; nj++) {
                int c = bn + wn * 32 + nj * 8 + cq;
                float2 v;
                v.x = acc[mi][nj][half * 2 + 0] + bias[c];
                v.y = acc[mi][nj][half * 2 + 1] + bias[c + 1];
                if (rrow) { v.x += rrow[c]; v.y += rrow[c + 1]; }
                *(float2*)&crow[c] = v;
            }
        }
    }
}

// ---------------- tensor-core windowed GQA attention (QT=64) ----------------
// S = QK^T in tf32; P,V in fp16 (11-bit mantissa ~ tf32); PV via ldmatrix.trans.
__global__ __launch_bounds__(256, 1) void attn_tc_kernel(const float* __restrict__ sinks,
                                                         const float* __restrict__ cosb,
                                                         const float* __restrict__ sinb) {
    extern __shared__ uint32_t shu[];
    uint32_t* Ku = shu;                              // [192][KSTR] tf32
    __half*   Vh = (__half*)(shu + ATT_K_W);         // [192][VSTRH] fp16
    uint32_t* Pu = shu + ATT_K_W + ATT_V_W;          // [8][32][PSTR]
    uint32_t vhb = smem_u32(shu) + ATT_K_W * 4;      // Vh smem byte address

    int nkv = blockIdx.y;
    int q0 = blockIdx.x * QT;
    int ks = q0 - SW; if (ks < 0) ks = 0;
    int nk = q0 + QT - ks;                    // multiple of 32
    int nchunk = nk >> 5;

    int tid = threadIdx.x, w = tid >> 5, lane = tid & 31;
    int head = w >> 1, qh = w & 1;

    // stage K: rope + tf32
    const float* kbase = g_qkv + H + nkv * HD;
    for (int idx = tid; idx < nk * 8; idx += 256) {
        int c = idx & 7;
        int row = idx >> 3;
        int t = ks + row;
        const float* base = kbase + (size_t)t * QKV_N;
        float4 lo = *(const float4*)(base + c * 4);
        float4 hi = *(const float4*)(base + 32 + c * 4);
        float4 cs = *(const float4*)(cosb + t * 32 + c * 4);
        float4 sn = *(const float4*)(sinb + t * 32 + c * 4);
        uint32_t* dst = Ku + row * KSTR + c * 4;
        dst[0] = f2tf32(lo.x * cs.x - hi.x * sn.x);
        dst[1] = f2tf32(lo.y * cs.y - hi.y * sn.y);
        dst[2] = f2tf32(lo.z * cs.z - hi.z * sn.z);
        dst[3] = f2tf32(lo.w * cs.w - hi.w * sn.w);
        dst[32] = f2tf32(hi.x * cs.x + lo.x * sn.x);
        dst[33] = f2tf32(hi.y * cs.y + lo.y * sn.y);
        dst[34] = f2tf32(hi.z * cs.z + lo.z * sn.z);
        dst[35] = f2tf32(hi.w * cs.w + lo.w * sn.w);
    }
    // stage V: fp16
    const float* vbase = g_qkv + H + NKV * HD + nkv * HD;
    for (int idx = tid; idx < nk * 16; idx += 256) {
        int r0 = idx >> 4, c4 = (idx & 15) << 2;
        float4 v = *(const float4*)(vbase + (size_t)(ks + r0) * QKV_N + c4);
        __half2* dst = (__half2*)(Vh + r0 * VSTRH + c4);
        dst[0] = __floats2half2_rn(v.x, v.y);
        dst[1] = __floats2half2_rn(v.z, v.w);
    }
    __syncthreads();

    int r = lane >> 2, kq = lane & 3;
    uint32_t* Pw = Pu + w * 32 * PSTR;

    // per-warp Q staging through own P slab: rope + scale(incl log2e) + tf32
    uint32_t af[2][8][4];
    {
        int tq = q0 + qh * 32 + lane;
        const float* qbase = g_qkv + (size_t)tq * QKV_N + (nkv * QM + head) * HD;
        #pragma unroll
        for (int h = 0; h < 2; h++) {
            #pragma unroll
            for (int c4 = 0; c4 < 8; c4++) {
                float4 lo = *(const float4*)(qbase + c4 * 4);
                float4 hi = *(const float4*)(qbase + 32 + c4 * 4);
                float4 cs = *(const float4*)(cosb + tq * 32 + c4 * 4);
                float4 sn = *(const float4*)(sinb + tq * 32 + c4 * 4);
                uint4 o;
                if (h == 0) {
                    o.x = f2tf32((lo.x * cs.x - hi.x * sn.x) * QSCALE);
                    o.y = f2tf32((lo.y * cs.y - hi.y * sn.y) * QSCALE);
                    o.z = f2tf32((lo.z * cs.z - hi.z * sn.z) * QSCALE);
                    o.w = f2tf32((lo.w * cs.w - hi.w * sn.w) * QSCALE);
                } else {
                    o.x = f2tf32((hi.x * cs.x + lo.x * sn.x) * QSCALE);
                    o.y = f2tf32((hi.y * cs.y + lo.y * sn.y) * QSCALE);
                    o.z = f2tf32((hi.z * cs.z + lo.z * sn.z) * QSCALE);
                    o.w = f2tf32((hi.w * cs.w + lo.w * sn.w) * QSCALE);
                }
                *(uint4*)&Pw[lane * PSTR + c4 * 4] = o;
            }
            __syncwarp();
            #pragma unroll
            for (int mt = 0; mt < 2; mt++)
                #pragma unroll
                for (int kt2 = 0; kt2 < 4; kt2++) {
                    int kt = h * 4 + kt2;
                    af[mt][kt][0] = Pw[(mt * 16 + r) * PSTR + kt2 * 8 + kq];
                    af[mt][kt][1] = Pw[(mt * 16 + r + 8) * PSTR + kt2 * 8 + kq];
                    af[mt][kt][2] = Pw[(mt * 16 + r) * PSTR + kt2 * 8 + kq + 4];
                    af[mt][kt][3] = Pw[(mt * 16 + r + 8) * PSTR + kt2 * 8 + kq + 4];
                }
            __syncwarp();
        }
    }

    float accO[2][8][4];
    #pragma unroll
    for (int mt = 0; mt < 2; mt++)
        #pragma unroll
        for (int nt = 0; nt < 8; nt++)
            #pragma unroll
            for (int e = 0; e < 4; e++) accO[mt][nt][e] = 0.f;
    float lsum[2][2] = {{0.f, 0.f}, {0.f, 0.f}};

    for (int c = 0; c < nchunk; c++) {
        // ---- S = Q @ K^T (tf32) ----
        float S[2][4][4];
        #pragma unroll
        for (int mt = 0; mt < 2; mt++)
            #pragma unroll
            for (int nt = 0; nt < 4; nt++)
                #pragma unroll
                for (int e = 0; e < 4; e++) S[mt][nt][e] = 0.f;
        #pragma unroll
        for (int nt = 0; nt < 4; nt++) {
            int key = c * 32 + nt * 8 + r;
            #pragma unroll
            for (int kt = 0; kt < 8; kt++) {
                uint32_t b[2];
                b[0] = Ku[key * KSTR + kt * 8 + kq];
                b[1] = Ku[key * KSTR + kt * 8 + kq + 4];
                mma_tf32(S[0][nt], af[0][kt], b);
                mma_tf32(S[1][nt], af[1][kt], b);
            }
        }
        // ---- mask + exp2 + row-sum; store P as fp16 pairs ----
        #pragma unroll
        for (int mt = 0; mt < 2; mt++)
            #pragma unroll
            for (int nt = 0; nt < 4; nt++) {
                #pragma unroll
                for (int e = 0; e < 4; e++) {
                    int half = e >> 1;
                    int q = q0 + qh * 32 + mt * 16 + r + half * 8;
                    int kp = ks + c * 32 + nt * 8 + 2 * kq + (e & 1);
                    float p = exp2f(S[mt][nt][e]);
                    p = ((unsigned)(q - kp) <= (unsigned)SW) ? p : 0.f;
                    lsum[mt][half] += p;
                    S[mt][nt][e] = p;
                }
                __half2 h0 = __floats2half2_rn(S[mt][nt][0], S[mt][nt][1]);
                __half2 h1 = __floats2half2_rn(S[mt][nt][2], S[mt][nt][3]);
                *(__half2*)&Pw[(mt * 16 + r) * PSTR + nt * 4 + kq] = h0;
                *(__half2*)&Pw[(mt * 16 + r + 8) * PSTR + nt * 4 + kq] = h1;
            }
        __syncwarp();
        // ---- O += P @ V (fp16 m16n8k16, V via ldmatrix.trans) ----
        #pragma unroll
        for (int kt = 0; kt < 2; kt++) {
            uint32_t pa[2][4];
            #pragma unroll
            for (int mt = 0; mt < 2; mt++) {
                pa[mt][0] = Pw[(mt * 16 + r) * PSTR + kt * 8 + kq];
                pa[mt][1] = Pw[(mt * 16 + r + 8) * PSTR + kt * 8 + kq];
                pa[mt][2] = Pw[(mt * 16 + r) * PSTR + kt * 8 + 4 + kq];
                pa[mt][3] = Pw[(mt * 16 + r + 8) * PSTR + kt * 8 + 4 + kq];
            }
            int vrow = c * 32 + kt * 16 + (lane & 7) + ((lane >> 3) & 1) * 8;
            #pragma unroll
            for (int nt2 = 0; nt2 < 4; nt2++) {
                int col = nt2 * 16 + (lane >> 4) * 8;
                uint32_t vb[4];
                ldsm4t(vb, vhb + (uint32_t)(vrow * VSTRH + col) * 2);
                mma_f16(accO[0][2 * nt2],     pa[0], vb);
                mma_f16(accO[0][2 * nt2 + 1], pa[0], vb + 2);
                mma_f16(accO[1][2 * nt2],     pa[1], vb);
                mma_f16(accO[1][2 * nt2 + 1], pa[1], vb + 2);
            }
        }
        __syncwarp();
    }

    float sk = exp2f(sinks[nkv * QM + head] * 1.44269504088896340736f);
    float inv[2][2];
    #pragma unroll
    for (int mt = 0; mt < 2; mt++)
        #pragma unroll
        for (int half = 0; half < 2; half++) {
            float l = lsum[mt][half];
            l += __shfl_xor_sync(0xffffffffu, l, 1);
            l += __shfl_xor_sync(0xffffffffu, l, 2);
            inv[mt][half] = 1.f / (l + sk);
        }

    int headcol = (nkv * QM + head) * HD;
    #pragma unroll
    for (int mt = 0; mt < 2; mt++)
        #pragma unroll
        for (int nt = 0; nt < 8; nt++) {
            int col = headcol + nt * 8 + 2 * kq;
            int q_a = q0 + qh * 32 + mt * 16 + r;
            int q_b = q_a + 8;
            *(__nv_bfloat162*)(g_attn + (size_t)q_a * H + col) =
                __floats2bfloat162_rn(accO[mt][nt][0] * inv[mt][0], accO[mt][nt][1] * inv[mt][0]);
            *(__nv_bfloat162*)(g_attn + (size_t)q_b * H + col) =
                __floats2bfloat162_rn(accO[mt][nt][2] * inv[mt][1], accO[mt][nt][3] * inv[mt][1]);
        }
}

// ---------------- launch -----------------------------------------------------
extern "C" void kernel_launch(void* const* d_in, const int* in_sizes, int n_in,
                              void* d_out, int out_size) {
    const float* x          = (const float*)d_in[0];
    const float* scale      = (const float*)d_in[1];
    const float* sinks      = (const float*)d_in[2];
    const float* qkv_kernel = (const float*)d_in[3];
    const float* qkv_bias   = (const float*)d_in[4];
    const float* out_kernel = (const float*)d_in[5];
    const float* out_bias   = (const float*)d_in[6];
    const float* cosb       = (const float*)d_in[7];
    const float* sinb       = (const float*)d_in[8];
    float* out = (float*)d_out;

    __nv_bfloat16 *pact, *pattn, *pqw, *pow;
    float* pq;
    cudaGetSymbolAddress((void**)&pact, g_act);
    cudaGetSymbolAddress((void**)&pq, g_qkv);
    cudaGetSymbolAddress((void**)&pattn, g_attn);
    cudaGetSymbolAddress((void**)&pqw, g_qkvw_t);
    cudaGetSymbolAddress((void**)&pow, g_outw_t);

    cudaFuncSetAttribute(attn_tc_kernel, cudaFuncAttributeMaxDynamicSharedMemorySize, ATT_SMEM);
    cudaFuncSetAttribute(gemm_tc_kernel, cudaFuncAttributeMaxDynamicSharedMemorySize, GEMM_SMEM);

    int prep_grid = T + (QKV_N / 32) * (H / 32);   // 8192 (rmsnorm + qkv transpose)
    prep_kernel<<<prep_grid, 256>>>(x, scale, qkv_kernel);
    // QKV GEMM + out-proj weight transpose folded into the tail wave
    gemm_tc_kernel<<<dim3(QKV_N / BN, T / BM + 11), 256, GEMM_SMEM>>>(
        pact, pqw, qkv_bias, nullptr, pq, QKV_N, H, out_kernel, pow);
    attn_tc_kernel<<<dim3(T / QT, NKV), 256, ATT_SMEM>>>(sinks, cosb, sinb);
    gemm_tc_kernel<<<dim3(H / BN, T / BM), 256, GEMM_SMEM>>>(
        pattn, pow, out_bias, x, out, H, H, nullptr, nullptr);
}